// round 3
// baseline (speedup 1.0000x reference)
#include <cuda_runtime.h>
#include <cuda_bf16.h>
#include <stdint.h>

#define E_EXP 8
#define D_DIM 1024
#define F_DIM 4096
#define T_TOK 4096
#define NSLOT (T_TOK * 2)

// ---------------- scratch (static __device__ arrays; no allocation) ----------------
__device__ __nv_bfloat16 g_xnb[(size_t)T_TOK * D_DIM];          // normalized x, bf16
__device__ __nv_bfloat16 g_w1b[(size_t)E_EXP * F_DIM * D_DIM];  // bf16(w1 * ln_w)
__device__ __nv_bfloat16 g_w3b[(size_t)E_EXP * F_DIM * D_DIM];  // bf16(w3 * ln_w)
__device__ __nv_bfloat16 g_w2b[(size_t)E_EXP * D_DIM * F_DIM];  // bf16(w2)
__device__ __nv_bfloat16 g_h[(size_t)NSLOT * F_DIM];            // gated activations
__device__ float         g_ys[(size_t)NSLOT * D_DIM];           // per-slot FFN output
__device__ int   g_cnt[E_EXP];
__device__ int   g_off[E_EXP];
__device__ int   g_cur[E_EXP];
__device__ int   g_perm[NSLOT];
__device__ int   g_tokE[NSLOT];
__device__ int   g_slot[NSLOT];
__device__ float g_gw[NSLOT];

// ---------------- small helpers ----------------
__device__ __forceinline__ void cp16(void* dst, const void* src) {
    uint32_t d = (uint32_t)__cvta_generic_to_shared(dst);
    asm volatile("cp.async.cg.shared.global [%0], [%1], 16;\n" :: "r"(d), "l"(src));
}
__device__ __forceinline__ void cp_commit() { asm volatile("cp.async.commit_group;\n" ::); }
__device__ __forceinline__ void cp_wait0()  { asm volatile("cp.async.wait_group 0;\n" ::); }

__device__ __forceinline__ void ldsm4(uint32_t* r, uint32_t a) {
    asm volatile("ldmatrix.sync.aligned.m8n8.x4.shared.b16 {%0,%1,%2,%3}, [%4];\n"
                 : "=r"(r[0]), "=r"(r[1]), "=r"(r[2]), "=r"(r[3]) : "r"(a));
}
__device__ __forceinline__ void mma16816(float* c, const uint32_t* a, uint32_t b0, uint32_t b1) {
    asm volatile(
        "mma.sync.aligned.m16n8k16.row.col.f32.bf16.bf16.f32 "
        "{%0,%1,%2,%3}, {%4,%5,%6,%7}, {%8,%9}, {%0,%1,%2,%3};\n"
        : "+f"(c[0]), "+f"(c[1]), "+f"(c[2]), "+f"(c[3])
        : "r"(a[0]), "r"(a[1]), "r"(a[2]), "r"(a[3]), "r"(b0), "r"(b1));
}
__device__ __forceinline__ float siluf(float v) { return v / (1.f + __expf(-v)); }

// ---------------- kernel 0: zero counters ----------------
__global__ void zero_kernel() {
    if (threadIdx.x < E_EXP) g_cnt[threadIdx.x] = 0;
}

// ---------------- kernel 1: gating + rmsnorm (one warp per token) ----------------
__global__ void __launch_bounds__(256) gate_kernel(const float* __restrict__ x,
                                                   const float* __restrict__ gw) {
    const int wid = threadIdx.x >> 5, lane = threadIdx.x & 31;
    const int t = blockIdx.x * 8 + wid;
    float xr[32];
    float ss = 0.f;
    const float* xp = x + (size_t)t * D_DIM + lane;
#pragma unroll
    for (int i = 0; i < 32; ++i) { xr[i] = xp[i * 32]; ss += xr[i] * xr[i]; }
    float sc[8];
#pragma unroll
    for (int e = 0; e < 8; ++e) {
        const float* gp = gw + e * D_DIM + lane;
        float s = 0.f;
#pragma unroll
        for (int i = 0; i < 32; ++i) s += xr[i] * gp[i * 32];
        sc[e] = s;
    }
#pragma unroll
    for (int o = 16; o > 0; o >>= 1) {
        ss += __shfl_xor_sync(0xffffffffu, ss, o);
#pragma unroll
        for (int e = 0; e < 8; ++e) sc[e] += __shfl_xor_sync(0xffffffffu, sc[e], o);
    }
    const float inv = rsqrtf(ss * (1.f / D_DIM) + 1e-6f);
    __nv_bfloat16* xo = g_xnb + (size_t)t * D_DIM + lane;
#pragma unroll
    for (int i = 0; i < 32; ++i) xo[i * 32] = __float2bfloat16(xr[i] * inv);

    if (lane == 0) {
        int i0 = 0; float v0 = sc[0];
#pragma unroll
        for (int e = 1; e < 8; ++e) if (sc[e] > v0) { v0 = sc[e]; i0 = e; }
        int i1 = (i0 == 0) ? 1 : 0; float v1 = sc[i1];
#pragma unroll
        for (int e = 0; e < 8; ++e)
            if (e != i0 && sc[e] > v1) { v1 = sc[e]; i1 = e; }
        const float e1 = __expf(v1 - v0);
        const float z  = 1.f + e1;
        g_tokE[2 * t] = i0; g_tokE[2 * t + 1] = i1;
        g_gw[2 * t] = 1.f / z; g_gw[2 * t + 1] = e1 / z;
        atomicAdd(&g_cnt[i0], 1);
        atomicAdd(&g_cnt[i1], 1);
    }
}

// ---------------- kernel 2: scan (tiny) ----------------
__global__ void scan_kernel() {
    int s = 0;
    for (int e = 0; e < E_EXP; ++e) { g_off[e] = s; g_cur[e] = s; s += g_cnt[e]; }
}

// ---------------- kernel 3: scatter tokens to expert slots ----------------
__global__ void scatter_kernel() {
    int t = blockIdx.x * blockDim.x + threadIdx.x;
    if (t >= T_TOK) return;
#pragma unroll
    for (int k = 0; k < 2; ++k) {
        int e = g_tokE[2 * t + k];
        int s = atomicAdd(&g_cur[e], 1);
        g_perm[s] = t;
        g_slot[2 * t + k] = s;
    }
}

// ---------------- kernel 4: weight conversion fp32 -> bf16 (fold ln into w1/w3) ----------------
__global__ void __launch_bounds__(256) conv13_kernel(const float* __restrict__ w1,
                                                     const float* __restrict__ w3,
                                                     const float* __restrict__ ln) {
    size_t i = ((size_t)blockIdx.x * 256 + threadIdx.x) * 4;
    int e = (int)(i >> 22);          // F*D = 2^22
    int d = (int)(i & (D_DIM - 1));
    float4 l = *reinterpret_cast<const float4*>(ln + (size_t)e * D_DIM + d);
    float4 a = *reinterpret_cast<const float4*>(w1 + i);
    float4 b = *reinterpret_cast<const float4*>(w3 + i);
    __nv_bfloat162* o1 = reinterpret_cast<__nv_bfloat162*>(g_w1b + i);
    __nv_bfloat162* o3 = reinterpret_cast<__nv_bfloat162*>(g_w3b + i);
    o1[0] = __floats2bfloat162_rn(a.x * l.x, a.y * l.y);
    o1[1] = __floats2bfloat162_rn(a.z * l.z, a.w * l.w);
    o3[0] = __floats2bfloat162_rn(b.x * l.x, b.y * l.y);
    o3[1] = __floats2bfloat162_rn(b.z * l.z, b.w * l.w);
}
__global__ void __launch_bounds__(256) conv2_kernel(const float* __restrict__ w2) {
    size_t i = ((size_t)blockIdx.x * 256 + threadIdx.x) * 4;
    float4 a = *reinterpret_cast<const float4*>(w2 + i);
    __nv_bfloat162* o = reinterpret_cast<__nv_bfloat162*>(g_w2b + i);
    o[0] = __floats2bfloat162_rn(a.x, a.y);
    o[1] = __floats2bfloat162_rn(a.z, a.w);
}

// ---------------- kernel 5: GEMM1 (xn @ w1^T, xn @ w3^T, fused silu-gate) ----------------
// CTA tile: M=128, N=64 (both matrices), K=32 per stage. 8 warps (4m x 2n).
__global__ void __launch_bounds__(256) gemm1_kernel() {
    __shared__ __align__(16) __nv_bfloat16 sA[2][128 * 40];
    __shared__ __align__(16) __nv_bfloat16 sB1[2][64 * 40];
    __shared__ __align__(16) __nv_bfloat16 sB3[2][64 * 40];
    __shared__ int rows[128];

    const int e = blockIdx.z;
    const int cnt = g_cnt[e];
    const int mtile = blockIdx.y;
    if (mtile * 128 >= cnt) return;
    const int ntile = blockIdx.x;
    const int off = g_off[e];
    const int tid = threadIdx.x;

    if (tid < 128) {
        int m = mtile * 128 + tid;
        rows[tid] = g_perm[off + (m < cnt ? m : cnt - 1)];
    }
    __syncthreads();

    const __nv_bfloat16* w1p = g_w1b + ((size_t)e * F_DIM + ntile * 64) * D_DIM;
    const __nv_bfloat16* w3p = g_w3b + ((size_t)e * F_DIM + ntile * 64) * D_DIM;

    const int lane = tid & 31;
    const int wid = tid >> 5;
    const int wm = wid & 3;
    const int wn = wid >> 2;

    float acc1[2][4][4], acc3[2][4][4];
#pragma unroll
    for (int a = 0; a < 2; ++a)
#pragma unroll
        for (int b = 0; b < 4; ++b)
#pragma unroll
            for (int c = 0; c < 4; ++c) { acc1[a][b][c] = 0.f; acc3[a][b][c] = 0.f; }

    const int lr = tid >> 2;        // 0..63
    const int lc = (tid & 3) * 8;   // half offset within K-tile

    auto load_stage = [&](int s, int kt) {
        const int k0 = kt * 32;
#pragma unroll
        for (int q = 0; q < 2; ++q) {
            int r = lr + q * 64;
            cp16(&sA[s][r * 40 + lc], g_xnb + (size_t)rows[r] * D_DIM + k0 + lc);
        }
        cp16(&sB1[s][lr * 40 + lc], w1p + (size_t)lr * D_DIM + k0 + lc);
        cp16(&sB3[s][lr * 40 + lc], w3p + (size_t)lr * D_DIM + k0 + lc);
        cp_commit();
    };

    const uint32_t aOff = ((wm * 32 + (lane & 15)) * 40 + (lane >> 4) * 8) * 2;
    const uint32_t bOff = ((((lane >> 4) & 1) * 8 + (lane & 7)) * 40 + ((lane >> 3) & 1) * 8) * 2;

    auto compute_stage = [&](int s) {
        uint32_t aBase  = (uint32_t)__cvta_generic_to_shared(&sA[s][0])  + aOff;
        uint32_t b1Base = (uint32_t)__cvta_generic_to_shared(&sB1[s][0]) + bOff + (uint32_t)(wn * 32 * 40 * 2);
        uint32_t b3Base = (uint32_t)__cvta_generic_to_shared(&sB3[s][0]) + bOff + (uint32_t)(wn * 32 * 40 * 2);
#pragma unroll
        for (int kk = 0; kk < 2; ++kk) {
            uint32_t a[2][4];
#pragma unroll
            for (int im = 0; im < 2; ++im)
                ldsm4(a[im], aBase + (im * 16 * 40 + kk * 16) * 2);
            uint32_t b1f[2][4], b3f[2][4];
#pragma unroll
            for (int i16 = 0; i16 < 2; ++i16) {
                ldsm4(b1f[i16], b1Base + (i16 * 16 * 40 + kk * 16) * 2);
                ldsm4(b3f[i16], b3Base + (i16 * 16 * 40 + kk * 16) * 2);
            }
#pragma unroll
            for (int im = 0; im < 2; ++im)
#pragma unroll
                for (int j = 0; j < 4; ++j) {
                    mma16816(acc1[im][j], a[im], b1f[j >> 1][(j & 1) * 2], b1f[j >> 1][(j & 1) * 2 + 1]);
                    mma16816(acc3[im][j], a[im], b3f[j >> 1][(j & 1) * 2], b3f[j >> 1][(j & 1) * 2 + 1]);
                }
        }
    };

    load_stage(0, 0);
    for (int kt = 0; kt < 32; ++kt) {
        cp_wait0();
        __syncthreads();
        if (kt + 1 < 32) load_stage((kt + 1) & 1, kt + 1);
        compute_stage(kt & 1);
    }

    const int mbase = mtile * 128 + wm * 32 + (lane >> 2);
    const int fbase = ntile * 64 + wn * 32 + (lane & 3) * 2;
#pragma unroll
    for (int im = 0; im < 2; ++im)
#pragma unroll
        for (int j = 0; j < 4; ++j)
#pragma unroll
            for (int hh = 0; hh < 2; ++hh) {
                int m = mbase + im * 16 + hh * 8;
                if (m < cnt) {
                    float v0 = siluf(acc1[im][j][hh * 2])     * acc3[im][j][hh * 2];
                    float v1 = siluf(acc1[im][j][hh * 2 + 1]) * acc3[im][j][hh * 2 + 1];
                    *reinterpret_cast<__nv_bfloat162*>(
                        &g_h[(size_t)(off + m) * F_DIM + fbase + j * 8]) =
                        __floats2bfloat162_rn(v0, v1);
                }
            }
}

// ---------------- kernel 6: GEMM2 (h @ w2^T -> ys) ----------------
// CTA tile: M=128, N=128, K=32 per stage. 8 warps (4m x 2n, warp tile 32x64).
__global__ void __launch_bounds__(256) gemm2_kernel() {
    __shared__ __align__(16) __nv_bfloat16 sA[2][128 * 40];
    __shared__ __align__(16) __nv_bfloat16 sB[2][128 * 40];
    __shared__ int rowsA[128];

    const int e = blockIdx.z;
    const int cnt = g_cnt[e];
    const int mtile = blockIdx.y;
    if (mtile * 128 >= cnt) return;
    const int ntile = blockIdx.x;     // 0..7
    const int off = g_off[e];
    const int tid = threadIdx.x;

    if (tid < 128) {
        int m = mtile * 128 + tid;
        rowsA[tid] = off + (m < cnt ? m : cnt - 1);
    }
    __syncthreads();

    const __nv_bfloat16* w2p = g_w2b + ((size_t)e * D_DIM + ntile * 128) * F_DIM;

    const int lane = tid & 31;
    const int wid = tid >> 5;
    const int wm = wid & 3;
    const int wn = wid >> 2;

    float acc[2][8][4];
#pragma unroll
    for (int a = 0; a < 2; ++a)
#pragma unroll
        for (int b = 0; b < 8; ++b)
#pragma unroll
            for (int c = 0; c < 4; ++c) acc[a][b][c] = 0.f;

    const int lr = tid >> 2;
    const int lc = (tid & 3) * 8;

    auto load_stage = [&](int s, int kt) {
        const int k0 = kt * 32;
#pragma unroll
        for (int q = 0; q < 2; ++q) {
            int r = lr + q * 64;
            cp16(&sA[s][r * 40 + lc], g_h + (size_t)rowsA[r] * F_DIM + k0 + lc);
            cp16(&sB[s][r * 40 + lc], w2p + (size_t)r * F_DIM + k0 + lc);
        }
        cp_commit();
    };

    const uint32_t aOff = ((wm * 32 + (lane & 15)) * 40 + (lane >> 4) * 8) * 2;
    const uint32_t bOff = ((((lane >> 4) & 1) * 8 + (lane & 7)) * 40 + ((lane >> 3) & 1) * 8) * 2;

    auto compute_stage = [&](int s) {
        uint32_t aBase = (uint32_t)__cvta_generic_to_shared(&sA[s][0]) + aOff;
        uint32_t bBase = (uint32_t)__cvta_generic_to_shared(&sB[s][0]) + bOff + (uint32_t)(wn * 64 * 40 * 2);
#pragma unroll
        for (int kk = 0; kk < 2; ++kk) {
            uint32_t a[2][4];
#pragma unroll
            for (int im = 0; im < 2; ++im)
                ldsm4(a[im], aBase + (im * 16 * 40 + kk * 16) * 2);
            uint32_t bf[4][4];
#pragma unroll
            for (int i16 = 0; i16 < 4; ++i16)
                ldsm4(bf[i16], bBase + (i16 * 16 * 40 + kk * 16) * 2);
#pragma unroll
            for (int im = 0; im < 2; ++im)
#pragma unroll
                for (int j = 0; j < 8; ++j)
                    mma16816(acc[im][j], a[im], bf[j >> 1][(j & 1) * 2], bf[j >> 1][(j & 1) * 2 + 1]);
        }
    };

    load_stage(0, 0);
    for (int kt = 0; kt < 128; ++kt) {
        cp_wait0();
        __syncthreads();
        if (kt + 1 < 128) load_stage((kt + 1) & 1, kt + 1);
        compute_stage(kt & 1);
    }

    const int mbase = mtile * 128 + wm * 32 + (lane >> 2);
    const int dbase = ntile * 128 + wn * 64 + (lane & 3) * 2;
#pragma unroll
    for (int im = 0; im < 2; ++im)
#pragma unroll
        for (int j = 0; j < 8; ++j)
#pragma unroll
            for (int hh = 0; hh < 2; ++hh) {
                int m = mbase + im * 16 + hh * 8;
                if (m < cnt) {
                    float2 v;
                    v.x = acc[im][j][hh * 2];
                    v.y = acc[im][j][hh * 2 + 1];
                    *reinterpret_cast<float2*>(
                        &g_ys[(size_t)(off + m) * D_DIM + dbase + j * 8]) = v;
                }
            }
}

// ---------------- kernel 7: combine (residual + weighted expert outputs) ----------------
__global__ void __launch_bounds__(256) combine_kernel(const float* __restrict__ x,
                                                      float* __restrict__ out) {
    const int t = blockIdx.x;
    const int s0 = g_slot[2 * t], s1 = g_slot[2 * t + 1];
    const float g0 = g_gw[2 * t], g1 = g_gw[2 * t + 1];
    const int d = threadIdx.x * 4;
    float4 xv = *reinterpret_cast<const float4*>(x + (size_t)t * D_DIM + d);
    float4 y0 = *reinterpret_cast<const float4*>(g_ys + (size_t)s0 * D_DIM + d);
    float4 y1 = *reinterpret_cast<const float4*>(g_ys + (size_t)s1 * D_DIM + d);
    float4 o;
    o.x = xv.x + g0 * y0.x + g1 * y1.x;
    o.y = xv.y + g0 * y0.y + g1 * y1.y;
    o.z = xv.z + g0 * y0.z + g1 * y1.z;
    o.w = xv.w + g0 * y0.w + g1 * y1.w;
    *reinterpret_cast<float4*>(out + (size_t)t * D_DIM + d) = o;
}

// ---------------- launch ----------------
extern "C" void kernel_launch(void* const* d_in, const int* in_sizes, int n_in,
                              void* d_out, int out_size) {
    (void)in_sizes; (void)n_in; (void)out_size;
    const float* x      = (const float*)d_in[0];
    const float* gate_w = (const float*)d_in[1];
    const float* ln_w   = (const float*)d_in[2];
    const float* w1     = (const float*)d_in[3];
    const float* w3     = (const float*)d_in[4];
    const float* w2     = (const float*)d_in[5];
    float* out = (float*)d_out;

    zero_kernel<<<1, 32>>>();
    gate_kernel<<<T_TOK / 8, 256>>>(x, gate_w);
    scan_kernel<<<1, 1>>>();
    scatter_kernel<<<(T_TOK + 255) / 256, 256>>>();
    conv13_kernel<<<(E_EXP * F_DIM * D_DIM) / 4 / 256, 256>>>(w1, w3, ln_w);
    conv2_kernel<<<(E_EXP * D_DIM * F_DIM) / 4 / 256, 256>>>(w2);
    gemm1_kernel<<<dim3(F_DIM / 64, T_TOK / 128, E_EXP), 256>>>();
    gemm2_kernel<<<dim3(D_DIM / 128, T_TOK / 128, E_EXP), 256>>>();
    combine_kernel<<<T_TOK, 256>>>(x, out);
}

// round 5
// speedup vs baseline: 1.3294x; 1.3294x over previous
#include <cuda_runtime.h>
#include <cuda_bf16.h>
#include <stdint.h>

#define E_EXP 8
#define D_DIM 1024
#define F_DIM 4096
#define T_TOK 4096
#define NSLOT (T_TOK * 2)

// ---------------- scratch (static __device__ arrays; no allocation) ----------------
__device__ __nv_bfloat16 g_xnb[(size_t)T_TOK * D_DIM];          // normalized x, bf16
__device__ __nv_bfloat16 g_w1b[(size_t)E_EXP * F_DIM * D_DIM];  // bf16(w1 * ln_w)
__device__ __nv_bfloat16 g_w3b[(size_t)E_EXP * F_DIM * D_DIM];  // bf16(w3 * ln_w)
__device__ __nv_bfloat16 g_w2b[(size_t)E_EXP * D_DIM * F_DIM];  // bf16(w2)
__device__ __nv_bfloat16 g_h[(size_t)NSLOT * F_DIM];            // gated activations
__device__ float         g_ys[(size_t)NSLOT * D_DIM];           // per-slot FFN output
__device__ int   g_cnt[E_EXP];
__device__ int   g_off[E_EXP];
__device__ int   g_cur[E_EXP];
__device__ int   g_perm[NSLOT];
__device__ int   g_tokE[NSLOT];
__device__ int   g_slot[NSLOT];
__device__ float g_gw[NSLOT];

// ---------------- small helpers ----------------
__device__ __forceinline__ void cp16s(uint32_t dst, const void* src) {
    asm volatile("cp.async.cg.shared.global [%0], [%1], 16;\n" :: "r"(dst), "l"(src));
}
__device__ __forceinline__ void cp_commit() { asm volatile("cp.async.commit_group;\n" ::: "memory"); }
template <int N>
__device__ __forceinline__ void cp_wait() { asm volatile("cp.async.wait_group %0;\n" :: "n"(N) : "memory"); }

__device__ __forceinline__ void ldsm4(uint32_t* r, uint32_t a) {
    asm volatile("ldmatrix.sync.aligned.m8n8.x4.shared.b16 {%0,%1,%2,%3}, [%4];\n"
                 : "=r"(r[0]), "=r"(r[1]), "=r"(r[2]), "=r"(r[3]) : "r"(a));
}
__device__ __forceinline__ void mma16816(float* c, const uint32_t* a, uint32_t b0, uint32_t b1) {
    asm volatile(
        "mma.sync.aligned.m16n8k16.row.col.f32.bf16.bf16.f32 "
        "{%0,%1,%2,%3}, {%4,%5,%6,%7}, {%8,%9}, {%0,%1,%2,%3};\n"
        : "+f"(c[0]), "+f"(c[1]), "+f"(c[2]), "+f"(c[3])
        : "r"(a[0]), "r"(a[1]), "r"(a[2]), "r"(a[3]), "r"(b0), "r"(b1));
}
__device__ __forceinline__ float siluf(float v) { return v / (1.f + __expf(-v)); }

// ---------------- kernel 0: zero counters ----------------
__global__ void zero_kernel() {
    if (threadIdx.x < E_EXP) g_cnt[threadIdx.x] = 0;
}

// ---------------- kernel 1: gating + rmsnorm (one warp per token) ----------------
__global__ void __launch_bounds__(256) gate_kernel(const float* __restrict__ x,
                                                   const float* __restrict__ gw) {
    const int wid = threadIdx.x >> 5, lane = threadIdx.x & 31;
    const int t = blockIdx.x * 8 + wid;
    float xr[32];
    float ss = 0.f;
    const float* xp = x + (size_t)t * D_DIM + lane;
#pragma unroll
    for (int i = 0; i < 32; ++i) { xr[i] = xp[i * 32]; ss += xr[i] * xr[i]; }
    float sc[8];
#pragma unroll
    for (int e = 0; e < 8; ++e) {
        const float* gp = gw + e * D_DIM + lane;
        float s = 0.f;
#pragma unroll
        for (int i = 0; i < 32; ++i) s += xr[i] * gp[i * 32];
        sc[e] = s;
    }
#pragma unroll
    for (int o = 16; o > 0; o >>= 1) {
        ss += __shfl_xor_sync(0xffffffffu, ss, o);
#pragma unroll
        for (int e = 0; e < 8; ++e) sc[e] += __shfl_xor_sync(0xffffffffu, sc[e], o);
    }
    const float inv = rsqrtf(ss * (1.f / D_DIM) + 1e-6f);
    __nv_bfloat16* xo = g_xnb + (size_t)t * D_DIM + lane;
#pragma unroll
    for (int i = 0; i < 32; ++i) xo[i * 32] = __float2bfloat16(xr[i] * inv);

    if (lane == 0) {
        int i0 = 0; float v0 = sc[0];
#pragma unroll
        for (int e = 1; e < 8; ++e) if (sc[e] > v0) { v0 = sc[e]; i0 = e; }
        int i1 = (i0 == 0) ? 1 : 0; float v1 = sc[i1];
#pragma unroll
        for (int e = 0; e < 8; ++e)
            if (e != i0 && sc[e] > v1) { v1 = sc[e]; i1 = e; }
        const float e1 = __expf(v1 - v0);
        const float z  = 1.f + e1;
        g_tokE[2 * t] = i0; g_tokE[2 * t + 1] = i1;
        g_gw[2 * t] = 1.f / z; g_gw[2 * t + 1] = e1 / z;
        atomicAdd(&g_cnt[i0], 1);
        atomicAdd(&g_cnt[i1], 1);
    }
}

// ---------------- kernel 2: scan (tiny) ----------------
__global__ void scan_kernel() {
    int s = 0;
    for (int e = 0; e < E_EXP; ++e) { g_off[e] = s; g_cur[e] = s; s += g_cnt[e]; }
}

// ---------------- kernel 3: scatter tokens to expert slots ----------------
__global__ void scatter_kernel() {
    int t = blockIdx.x * blockDim.x + threadIdx.x;
    if (t >= T_TOK) return;
#pragma unroll
    for (int k = 0; k < 2; ++k) {
        int e = g_tokE[2 * t + k];
        int s = atomicAdd(&g_cur[e], 1);
        g_perm[s] = t;
        g_slot[2 * t + k] = s;
    }
}

// ---------------- kernel 4: weight conversion fp32 -> bf16 (fold ln into w1/w3) ----------------
__global__ void __launch_bounds__(256) conv13_kernel(const float* __restrict__ w1,
                                                     const float* __restrict__ w3,
                                                     const float* __restrict__ ln) {
    size_t i = ((size_t)blockIdx.x * 256 + threadIdx.x) * 4;
    int e = (int)(i >> 22);          // F*D = 2^22
    int d = (int)(i & (D_DIM - 1));
    float4 l = *reinterpret_cast<const float4*>(ln + (size_t)e * D_DIM + d);
    float4 a = *reinterpret_cast<const float4*>(w1 + i);
    float4 b = *reinterpret_cast<const float4*>(w3 + i);
    __nv_bfloat162* o1 = reinterpret_cast<__nv_bfloat162*>(g_w1b + i);
    __nv_bfloat162* o3 = reinterpret_cast<__nv_bfloat162*>(g_w3b + i);
    o1[0] = __floats2bfloat162_rn(a.x * l.x, a.y * l.y);
    o1[1] = __floats2bfloat162_rn(a.z * l.z, a.w * l.w);
    o3[0] = __floats2bfloat162_rn(b.x * l.x, b.y * l.y);
    o3[1] = __floats2bfloat162_rn(b.z * l.z, b.w * l.w);
}
__global__ void __launch_bounds__(256) conv2_kernel(const float* __restrict__ w2) {
    size_t i = ((size_t)blockIdx.x * 256 + threadIdx.x) * 4;
    float4 a = *reinterpret_cast<const float4*>(w2 + i);
    __nv_bfloat162* o = reinterpret_cast<__nv_bfloat162*>(g_w2b + i);
    o[0] = __floats2bfloat162_rn(a.x, a.y);
    o[1] = __floats2bfloat162_rn(a.z, a.w);
}

// ================= GEMM settings =================
// K-stage = 64 (128B rows, XOR-swizzled). 4 smem stages, prefetch 3, wait_group 2.
#define KSTAGE 64
#define NBUF   4

// gemm1 stage: A 128x64 bf16 (16KB) + B1 64x64 (8KB) + B3 64x64 (8KB) = 32KB
#define G1_STAGE 32768
#define G1_SMEM  (1024 + NBUF * G1_STAGE)
// gemm2 stage: A 128x64 (16KB) + B 128x64 (16KB) = 32KB
#define G2_STAGE 32768
#define G2_SMEM  (1024 + NBUF * G2_STAGE)

// ---------------- kernel 5: GEMM1 (xn @ w1^T, xn @ w3^T, fused silu-gate) ----------------
// CTA tile: M=128, N=64 per matrix. 8 warps (4m x 2n), warp tile 32x32 per matrix.
__global__ void __launch_bounds__(256) gemm1_kernel() {
    extern __shared__ __align__(128) char smem[];
    const int e = blockIdx.z;
    const int cnt = g_cnt[e];
    const int mtile = blockIdx.y;
    if (mtile * 128 >= cnt) return;
    const int ntile = blockIdx.x;
    const int off = g_off[e];
    const int tid = threadIdx.x;
    const int lane = tid & 31;
    const int w = tid >> 5;
    const int wm = w & 3, wn = w >> 2;

    int* rows = (int*)smem;
    const uint32_t sb = (uint32_t)__cvta_generic_to_shared(smem);
    const uint32_t dataB = sb + 1024;

    if (tid < 128) {
        int m = mtile * 128 + tid;
        rows[tid] = g_perm[off + (m < cnt ? m : cnt - 1)];
    }
    __syncthreads();

    const __nv_bfloat16* w1p = g_w1b + ((size_t)e * F_DIM + (size_t)ntile * 64) * D_DIM;
    const __nv_bfloat16* w3p = g_w3b + ((size_t)e * F_DIM + (size_t)ntile * 64) * D_DIM;

    const int rr = tid >> 3;    // 0..31 row group
    const int cc = tid & 7;     // 16B chunk in 128B row
    const uint32_t swoff = (uint32_t)cc << 4;

    auto load_stage = [&](int buf, int kt) {
        const uint32_t base = dataB + (uint32_t)buf * G1_STAGE;
        const int k0 = kt * KSTAGE;
#pragma unroll
        for (int p = 0; p < 4; ++p) {            // A: 128 rows
            int r = p * 32 + rr;
            uint32_t dst = base + (uint32_t)(r << 7) + (swoff ^ ((uint32_t)(r & 7) << 4));
            cp16s(dst, g_xnb + (size_t)rows[r] * D_DIM + k0 + cc * 8);
        }
#pragma unroll
        for (int p = 0; p < 2; ++p) {            // B1, B3: 64 rows each
            int r = p * 32 + rr;
            uint32_t so = (uint32_t)(r << 7) + (swoff ^ ((uint32_t)(r & 7) << 4));
            cp16s(base + 16384 + so, w1p + (size_t)r * D_DIM + k0 + cc * 8);
            cp16s(base + 24576 + so, w3p + (size_t)r * D_DIM + k0 + cc * 8);
        }
        cp_commit();
    };

    float acc1[2][4][4], acc3[2][4][4];
#pragma unroll
    for (int a = 0; a < 2; ++a)
#pragma unroll
        for (int b = 0; b < 4; ++b)
#pragma unroll
            for (int c = 0; c < 4; ++c) { acc1[a][b][c] = 0.f; acc3[a][b][c] = 0.f; }

    // fragment lane addressing (128B rows, XOR swizzle by (row&7))
    const int sx  = lane & 7;                    // swizzle index (row&7 for all our frag rows)
    const int hiA = lane >> 4;                   // A: k-half select
    const int rA  = wm * 32 + (lane & 15);       // A frag row (im adds +16)
    const int hiB = (lane >> 3) & 1;             // B: k-half select
    const int rB  = wn * 32 + ((lane >> 4) & 1) * 8 + (lane & 7);  // B frag row (i16 adds +16)
    const uint32_t aRow0 = (uint32_t)(rA << 7), aRow1 = (uint32_t)((rA + 16) << 7);
    const uint32_t bRow0 = (uint32_t)(rB << 7), bRow1 = (uint32_t)((rB + 16) << 7);

    auto compute_stage = [&](int buf) {
        const uint32_t base = dataB + (uint32_t)buf * G1_STAGE;
        const uint32_t Ab = base, B1b = base + 16384, B3b = base + 24576;
#pragma unroll
        for (int kk = 0; kk < 4; ++kk) {
            const uint32_t ao = (uint32_t)(((2 * kk + hiA) ^ sx) << 4);
            const uint32_t bo = (uint32_t)(((2 * kk + hiB) ^ sx) << 4);
            uint32_t a[2][4];
            ldsm4(a[0], Ab + aRow0 + ao);
            ldsm4(a[1], Ab + aRow1 + ao);
            uint32_t b1f[2][4], b3f[2][4];
            ldsm4(b1f[0], B1b + bRow0 + bo);
            ldsm4(b1f[1], B1b + bRow1 + bo);
            ldsm4(b3f[0], B3b + bRow0 + bo);
            ldsm4(b3f[1], B3b + bRow1 + bo);
#pragma unroll
            for (int im = 0; im < 2; ++im)
#pragma unroll
                for (int j = 0; j < 4; ++j) {
                    mma16816(acc1[im][j], a[im], b1f[j >> 1][(j & 1) * 2], b1f[j >> 1][(j & 1) * 2 + 1]);
                    mma16816(acc3[im][j], a[im], b3f[j >> 1][(j & 1) * 2], b3f[j >> 1][(j & 1) * 2 + 1]);
                }
        }
    };

    const int NK = D_DIM / KSTAGE;   // 16
    load_stage(0, 0);
    load_stage(1, 1);
    load_stage(2, 2);
    for (int kt = 0; kt < NK; ++kt) {
        if (kt < NK - 2)      cp_wait<2>();
        else if (kt == NK - 2) cp_wait<1>();
        else                   cp_wait<0>();
        __syncthreads();
        if (kt + 3 < NK) load_stage((kt + 3) & (NBUF - 1), kt + 3);
        compute_stage(kt & (NBUF - 1));
    }

    const int mbase = mtile * 128 + wm * 32 + (lane >> 2);
    const int fbase = ntile * 64 + wn * 32 + (lane & 3) * 2;
#pragma unroll
    for (int im = 0; im < 2; ++im)
#pragma unroll
        for (int j = 0; j < 4; ++j)
#pragma unroll
            for (int hh = 0; hh < 2; ++hh) {
                int m = mbase + im * 16 + hh * 8;
                if (m < cnt) {
                    float v0 = siluf(acc1[im][j][hh * 2])     * acc3[im][j][hh * 2];
                    float v1 = siluf(acc1[im][j][hh * 2 + 1]) * acc3[im][j][hh * 2 + 1];
                    *reinterpret_cast<__nv_bfloat162*>(
                        &g_h[(size_t)(off + m) * F_DIM + fbase + j * 8]) =
                        __floats2bfloat162_rn(v0, v1);
                }
            }
}

// ---------------- kernel 6: GEMM2 (h @ w2^T -> ys) ----------------
// CTA tile: M=128, N=128. 8 warps (4m x 2n), warp tile 32x64.
__global__ void __launch_bounds__(256) gemm2_kernel() {
    extern __shared__ __align__(128) char smem[];
    const int e = blockIdx.z;
    const int cnt = g_cnt[e];
    const int mtile = blockIdx.y;
    if (mtile * 128 >= cnt) return;
    const int ntile = blockIdx.x;     // 0..7
    const int off = g_off[e];
    const int tid = threadIdx.x;
    const int lane = tid & 31;
    const int w = tid >> 5;
    const int wm = w & 3, wn = w >> 2;

    int* rowsA = (int*)smem;
    const uint32_t sb = (uint32_t)__cvta_generic_to_shared(smem);
    const uint32_t dataB = sb + 1024;

    if (tid < 128) {
        int m = mtile * 128 + tid;
        rowsA[tid] = off + (m < cnt ? m : cnt - 1);
    }
    __syncthreads();

    const __nv_bfloat16* w2p = g_w2b + ((size_t)e * D_DIM + (size_t)ntile * 128) * F_DIM;

    const int rr = tid >> 3;
    const int cc = tid & 7;
    const uint32_t swoff = (uint32_t)cc << 4;

    auto load_stage = [&](int buf, int kt) {
        const uint32_t base = dataB + (uint32_t)buf * G2_STAGE;
        const int k0 = kt * KSTAGE;
#pragma unroll
        for (int p = 0; p < 4; ++p) {            // A: 128 rows of h
            int r = p * 32 + rr;
            uint32_t so = (uint32_t)(r << 7) + (swoff ^ ((uint32_t)(r & 7) << 4));
            cp16s(base + so, g_h + (size_t)rowsA[r] * F_DIM + k0 + cc * 8);
        }
#pragma unroll
        for (int p = 0; p < 4; ++p) {            // B: 128 rows of w2
            int r = p * 32 + rr;
            uint32_t so = (uint32_t)(r << 7) + (swoff ^ ((uint32_t)(r & 7) << 4));
            cp16s(base + 16384 + so, w2p + (size_t)r * F_DIM + k0 + cc * 8);
        }
        cp_commit();
    };

    float acc[2][8][4];
#pragma unroll
    for (int a = 0; a < 2; ++a)
#pragma unroll
        for (int b = 0; b < 8; ++b)
#pragma unroll
            for (int c = 0; c < 4; ++c) acc[a][b][c] = 0.f;

    const int sx  = lane & 7;
    const int hiA = lane >> 4;
    const int rA  = wm * 32 + (lane & 15);
    const int hiB = (lane >> 3) & 1;
    const int rB  = wn * 64 + ((lane >> 4) & 1) * 8 + (lane & 7);
    const uint32_t aRow0 = (uint32_t)(rA << 7), aRow1 = (uint32_t)((rA + 16) << 7);
    uint32_t bRow[4];
#pragma unroll
    for (int i = 0; i < 4; ++i) bRow[i] = (uint32_t)((rB + i * 16) << 7);

    auto compute_stage = [&](int buf) {
        const uint32_t base = dataB + (uint32_t)buf * G2_STAGE;
        const uint32_t Ab = base, Bb = base + 16384;
#pragma unroll
        for (int kk = 0; kk < 4; ++kk) {
            const uint32_t ao = (uint32_t)(((2 * kk + hiA) ^ sx) << 4);
            const uint32_t bo = (uint32_t)(((2 * kk + hiB) ^ sx) << 4);
            uint32_t a[2][4];
            ldsm4(a[0], Ab + aRow0 + ao);
            ldsm4(a[1], Ab + aRow1 + ao);
            uint32_t bf[4][4];
#pragma unroll
            for (int i16 = 0; i16 < 4; ++i16)
                ldsm4(bf[i16], Bb + bRow[i16] + bo);
#pragma unroll
            for (int im = 0; im < 2; ++im)
#pragma unroll
                for (int j = 0; j < 8; ++j)
                    mma16816(acc[im][j], a[im], bf[j >> 1][(j & 1) * 2], bf[j >> 1][(j & 1) * 2 + 1]);
        }
    };

    const int NK = F_DIM / KSTAGE;   // 64
    load_stage(0, 0);
    load_stage(1, 1);
    load_stage(2, 2);
    for (int kt = 0; kt < NK; ++kt) {
        if (kt < NK - 2)       cp_wait<2>();
        else if (kt == NK - 2) cp_wait<1>();
        else                   cp_wait<0>();
        __syncthreads();
        if (kt + 3 < NK) load_stage((kt + 3) & (NBUF - 1), kt + 3);
        compute_stage(kt & (NBUF - 1));
    }

    const int mbase = mtile * 128 + wm * 32 + (lane >> 2);
    const int dbase = ntile * 128 + wn * 64 + (lane & 3) * 2;
#pragma unroll
    for (int im = 0; im < 2; ++im)
#pragma unroll
        for (int j = 0; j < 8; ++j)
#pragma unroll
            for (int hh = 0; hh < 2; ++hh) {
                int m = mbase + im * 16 + hh * 8;
                if (m < cnt) {
                    float2 v;
                    v.x = acc[im][j][hh * 2];
                    v.y = acc[im][j][hh * 2 + 1];
                    *reinterpret_cast<float2*>(
                        &g_ys[(size_t)(off + m) * D_DIM + dbase + j * 8]) = v;
                }
            }
}

// ---------------- kernel 7: combine (residual + weighted expert outputs) ----------------
__global__ void __launch_bounds__(256) combine_kernel(const float* __restrict__ x,
                                                      float* __restrict__ out) {
    const int t = blockIdx.x;
    const int s0 = g_slot[2 * t], s1 = g_slot[2 * t + 1];
    const float g0 = g_gw[2 * t], g1 = g_gw[2 * t + 1];
    const int d = threadIdx.x * 4;
    float4 xv = *reinterpret_cast<const float4*>(x + (size_t)t * D_DIM + d);
    float4 y0 = *reinterpret_cast<const float4*>(g_ys + (size_t)s0 * D_DIM + d);
    float4 y1 = *reinterpret_cast<const float4*>(g_ys + (size_t)s1 * D_DIM + d);
    float4 o;
    o.x = xv.x + g0 * y0.x + g1 * y1.x;
    o.y = xv.y + g0 * y0.y + g1 * y1.y;
    o.z = xv.z + g0 * y0.z + g1 * y1.z;
    o.w = xv.w + g0 * y0.w + g1 * y1.w;
    *reinterpret_cast<float4*>(out + (size_t)t * D_DIM + d) = o;
}

// ---------------- launch ----------------
extern "C" void kernel_launch(void* const* d_in, const int* in_sizes, int n_in,
                              void* d_out, int out_size) {
    (void)in_sizes; (void)n_in; (void)out_size;
    const float* x      = (const float*)d_in[0];
    const float* gate_w = (const float*)d_in[1];
    const float* ln_w   = (const float*)d_in[2];
    const float* w1     = (const float*)d_in[3];
    const float* w3     = (const float*)d_in[4];
    const float* w2     = (const float*)d_in[5];
    float* out = (float*)d_out;

    cudaFuncSetAttribute(gemm1_kernel, cudaFuncAttributeMaxDynamicSharedMemorySize, G1_SMEM);
    cudaFuncSetAttribute(gemm2_kernel, cudaFuncAttributeMaxDynamicSharedMemorySize, G2_SMEM);

    zero_kernel<<<1, 32>>>();
    gate_kernel<<<T_TOK / 8, 256>>>(x, gate_w);
    scan_kernel<<<1, 1>>>();
    scatter_kernel<<<(T_TOK + 255) / 256, 256>>>();
    conv13_kernel<<<(E_EXP * F_DIM * D_DIM) / 4 / 256, 256>>>(w1, w3, ln_w);
    conv2_kernel<<<(E_EXP * D_DIM * F_DIM) / 4 / 256, 256>>>(w2);
    gemm1_kernel<<<dim3(F_DIM / 64, T_TOK / 128, E_EXP), 256, G1_SMEM>>>();
    gemm2_kernel<<<dim3(D_DIM / 128, T_TOK / 128, E_EXP), 256, G2_SMEM>>>();
    combine_kernel<<<T_TOK, 256>>>(x, out);
}

// round 6
// speedup vs baseline: 1.3453x; 1.0120x over previous
#include <cuda_runtime.h>
#include <cuda_bf16.h>
#include <stdint.h>

#define E_EXP 8
#define D_DIM 1024
#define F_DIM 4096
#define T_TOK 4096
#define NSLOT (T_TOK * 2)

// ---------------- scratch (static __device__ arrays; no allocation) ----------------
__device__ __nv_bfloat16 g_xnb[(size_t)T_TOK * D_DIM];          // normalized x, bf16
__device__ __nv_bfloat16 g_w1b[(size_t)E_EXP * F_DIM * D_DIM];  // bf16(w1 * ln_w)
__device__ __nv_bfloat16 g_w3b[(size_t)E_EXP * F_DIM * D_DIM];  // bf16(w3 * ln_w)
__device__ __nv_bfloat16 g_w2b[(size_t)E_EXP * D_DIM * F_DIM];  // bf16(w2)
__device__ __nv_bfloat16 g_h[(size_t)NSLOT * F_DIM];            // gated activations
__device__ float         g_ys[(size_t)NSLOT * D_DIM];           // per-slot FFN output
__device__ int   g_cnt[E_EXP];
__device__ int   g_off[E_EXP];
__device__ int   g_cur[E_EXP];
__device__ int   g_perm[NSLOT];
__device__ int   g_tokE[NSLOT];
__device__ int   g_slot[NSLOT];
__device__ float g_gw[NSLOT];

// ---------------- small helpers ----------------
__device__ __forceinline__ void cp16s(uint32_t dst, const void* src) {
    asm volatile("cp.async.cg.shared.global [%0], [%1], 16;\n" :: "r"(dst), "l"(src));
}
__device__ __forceinline__ void cp_commit() { asm volatile("cp.async.commit_group;\n" ::: "memory"); }
template <int N>
__device__ __forceinline__ void cp_wait() { asm volatile("cp.async.wait_group %0;\n" :: "n"(N) : "memory"); }

__device__ __forceinline__ void ldsm4(uint32_t* r, uint32_t a) {
    asm volatile("ldmatrix.sync.aligned.m8n8.x4.shared.b16 {%0,%1,%2,%3}, [%4];\n"
                 : "=r"(r[0]), "=r"(r[1]), "=r"(r[2]), "=r"(r[3]) : "r"(a));
}
__device__ __forceinline__ void mma16816(float* c, const uint32_t* a, uint32_t b0, uint32_t b1) {
    asm volatile(
        "mma.sync.aligned.m16n8k16.row.col.f32.bf16.bf16.f32 "
        "{%0,%1,%2,%3}, {%4,%5,%6,%7}, {%8,%9}, {%0,%1,%2,%3};\n"
        : "+f"(c[0]), "+f"(c[1]), "+f"(c[2]), "+f"(c[3])
        : "r"(a[0]), "r"(a[1]), "r"(a[2]), "r"(a[3]), "r"(b0), "r"(b1));
}
__device__ __forceinline__ float siluf(float v) { return v / (1.f + __expf(-v)); }

// ---------------- kernel 0: zero counters ----------------
__global__ void zero_kernel() {
    if (threadIdx.x < E_EXP) g_cnt[threadIdx.x] = 0;
}

// ---------------- kernel 1: gating + rmsnorm (one warp per token) ----------------
__global__ void __launch_bounds__(256) gate_kernel(const float* __restrict__ x,
                                                   const float* __restrict__ gw) {
    const int wid = threadIdx.x >> 5, lane = threadIdx.x & 31;
    const int t = blockIdx.x * 8 + wid;
    float xr[32];
    float ss = 0.f;
    const float* xp = x + (size_t)t * D_DIM + lane;
#pragma unroll
    for (int i = 0; i < 32; ++i) { xr[i] = xp[i * 32]; ss += xr[i] * xr[i]; }
    float sc[8];
#pragma unroll
    for (int e = 0; e < 8; ++e) {
        const float* gp = gw + e * D_DIM + lane;
        float s = 0.f;
#pragma unroll
        for (int i = 0; i < 32; ++i) s += xr[i] * gp[i * 32];
        sc[e] = s;
    }
#pragma unroll
    for (int o = 16; o > 0; o >>= 1) {
        ss += __shfl_xor_sync(0xffffffffu, ss, o);
#pragma unroll
        for (int e = 0; e < 8; ++e) sc[e] += __shfl_xor_sync(0xffffffffu, sc[e], o);
    }
    const float inv = rsqrtf(ss * (1.f / D_DIM) + 1e-6f);
    __nv_bfloat16* xo = g_xnb + (size_t)t * D_DIM + lane;
#pragma unroll
    for (int i = 0; i < 32; ++i) xo[i * 32] = __float2bfloat16(xr[i] * inv);

    if (lane == 0) {
        int i0 = 0; float v0 = sc[0];
#pragma unroll
        for (int e = 1; e < 8; ++e) if (sc[e] > v0) { v0 = sc[e]; i0 = e; }
        int i1 = (i0 == 0) ? 1 : 0; float v1 = sc[i1];
#pragma unroll
        for (int e = 0; e < 8; ++e)
            if (e != i0 && sc[e] > v1) { v1 = sc[e]; i1 = e; }
        const float e1 = __expf(v1 - v0);
        const float z  = 1.f + e1;
        g_tokE[2 * t] = i0; g_tokE[2 * t + 1] = i1;
        g_gw[2 * t] = 1.f / z; g_gw[2 * t + 1] = e1 / z;
        atomicAdd(&g_cnt[i0], 1);
        atomicAdd(&g_cnt[i1], 1);
    }
}

// ---------------- kernel 2: scan (tiny) ----------------
__global__ void scan_kernel() {
    int s = 0;
    for (int e = 0; e < E_EXP; ++e) { g_off[e] = s; g_cur[e] = s; s += g_cnt[e]; }
}

// ---------------- kernel 3: scatter tokens to expert slots ----------------
__global__ void scatter_kernel() {
    int t = blockIdx.x * blockDim.x + threadIdx.x;
    if (t >= T_TOK) return;
#pragma unroll
    for (int k = 0; k < 2; ++k) {
        int e = g_tokE[2 * t + k];
        int s = atomicAdd(&g_cur[e], 1);
        g_perm[s] = t;
        g_slot[2 * t + k] = s;
    }
}

// ---------------- kernel 4: weight conversion fp32 -> bf16 (fold ln into w1/w3) ----------------
__global__ void __launch_bounds__(256) conv_all_kernel(const float* __restrict__ w1,
                                                       const float* __restrict__ w3,
                                                       const float* __restrict__ w2,
                                                       const float* __restrict__ ln) {
    size_t i = ((size_t)blockIdx.x * 256 + threadIdx.x) * 4;
    if (blockIdx.y == 0) {
        int e = (int)(i >> 22);          // F*D = 2^22
        int d = (int)(i & (D_DIM - 1));
        float4 l = *reinterpret_cast<const float4*>(ln + (size_t)e * D_DIM + d);
        float4 a = *reinterpret_cast<const float4*>(w1 + i);
        float4 b = *reinterpret_cast<const float4*>(w3 + i);
        __nv_bfloat162* o1 = reinterpret_cast<__nv_bfloat162*>(g_w1b + i);
        __nv_bfloat162* o3 = reinterpret_cast<__nv_bfloat162*>(g_w3b + i);
        o1[0] = __floats2bfloat162_rn(a.x * l.x, a.y * l.y);
        o1[1] = __floats2bfloat162_rn(a.z * l.z, a.w * l.w);
        o3[0] = __floats2bfloat162_rn(b.x * l.x, b.y * l.y);
        o3[1] = __floats2bfloat162_rn(b.z * l.z, b.w * l.w);
    } else {
        float4 a = *reinterpret_cast<const float4*>(w2 + i);
        __nv_bfloat162* o = reinterpret_cast<__nv_bfloat162*>(g_w2b + i);
        o[0] = __floats2bfloat162_rn(a.x, a.y);
        o[1] = __floats2bfloat162_rn(a.z, a.w);
    }
}

// ================= GEMM settings =================
#define KSTAGE 64
#define NBUF   4
#define G1_STAGE 32768
#define G1_SMEM  (1024 + NBUF * G1_STAGE)
#define G2_STAGE 32768
#define G2_SMEM  (1024 + NBUF * G2_STAGE)

// ---------------- kernel 5: GEMM1 (xn @ w1^T, xn @ w3^T, fused silu-gate) ----------------
// CTA tile: M=128, N=64 per matrix. 8 warps (4m x 2n), warp tile 32x32 per matrix.
// Register-double-buffered fragments inside each 64-K stage.
__global__ void __launch_bounds__(256) gemm1_kernel() {
    extern __shared__ __align__(128) char smem[];
    const int e = blockIdx.z;
    const int cnt = g_cnt[e];
    const int mtile = blockIdx.y;
    if (mtile * 128 >= cnt) return;
    const int ntile = blockIdx.x;
    const int off = g_off[e];
    const int tid = threadIdx.x;
    const int lane = tid & 31;
    const int w = tid >> 5;
    const int wm = w & 3, wn = w >> 2;

    int* rows = (int*)smem;
    const uint32_t sb = (uint32_t)__cvta_generic_to_shared(smem);
    const uint32_t dataB = sb + 1024;

    if (tid < 128) {
        int m = mtile * 128 + tid;
        rows[tid] = g_perm[off + (m < cnt ? m : cnt - 1)];
    }
    __syncthreads();

    const __nv_bfloat16* w1p = g_w1b + ((size_t)e * F_DIM + (size_t)ntile * 64) * D_DIM;
    const __nv_bfloat16* w3p = g_w3b + ((size_t)e * F_DIM + (size_t)ntile * 64) * D_DIM;

    const int rr = tid >> 3;    // row group
    const int cc = tid & 7;     // 16B chunk
    const uint32_t swoff = (uint32_t)cc << 4;

    auto load_stage = [&](int buf, int kt) {
        const uint32_t base = dataB + (uint32_t)buf * G1_STAGE;
        const int k0 = kt * KSTAGE;
#pragma unroll
        for (int p = 0; p < 4; ++p) {            // A: 128 rows
            int r = p * 32 + rr;
            uint32_t dst = base + (uint32_t)(r << 7) + (swoff ^ ((uint32_t)(r & 7) << 4));
            cp16s(dst, g_xnb + (size_t)rows[r] * D_DIM + k0 + cc * 8);
        }
#pragma unroll
        for (int p = 0; p < 2; ++p) {            // B1, B3: 64 rows each
            int r = p * 32 + rr;
            uint32_t so = (uint32_t)(r << 7) + (swoff ^ ((uint32_t)(r & 7) << 4));
            cp16s(base + 16384 + so, w1p + (size_t)r * D_DIM + k0 + cc * 8);
            cp16s(base + 24576 + so, w3p + (size_t)r * D_DIM + k0 + cc * 8);
        }
        cp_commit();
    };

    float acc1[2][4][4], acc3[2][4][4];
#pragma unroll
    for (int a = 0; a < 2; ++a)
#pragma unroll
        for (int b = 0; b < 4; ++b)
#pragma unroll
            for (int c = 0; c < 4; ++c) { acc1[a][b][c] = 0.f; acc3[a][b][c] = 0.f; }

    const int sx  = lane & 7;
    const int hiA = lane >> 4;
    const int rA  = wm * 32 + (lane & 15);
    const int hiB = (lane >> 3) & 1;
    const int rB  = wn * 32 + ((lane >> 4) & 1) * 8 + (lane & 7);
    const uint32_t aRow0 = (uint32_t)(rA << 7), aRow1 = (uint32_t)((rA + 16) << 7);
    const uint32_t bRow0 = (uint32_t)(rB << 7), bRow1 = (uint32_t)((rB + 16) << 7);

    auto compute_stage = [&](int buf) {
        const uint32_t base = dataB + (uint32_t)buf * G1_STAGE;
        const uint32_t Ab = base, B1b = base + 16384, B3b = base + 24576;
        uint32_t a[2][2][4], b1f[2][2][4], b3f[2][2][4];
        {   // preload kk=0 fragments
            const uint32_t ao = (uint32_t)((hiA ^ sx) << 4);
            const uint32_t bo = (uint32_t)((hiB ^ sx) << 4);
            ldsm4(a[0][0], Ab + aRow0 + ao);
            ldsm4(a[0][1], Ab + aRow1 + ao);
            ldsm4(b1f[0][0], B1b + bRow0 + bo);
            ldsm4(b1f[0][1], B1b + bRow1 + bo);
            ldsm4(b3f[0][0], B3b + bRow0 + bo);
            ldsm4(b3f[0][1], B3b + bRow1 + bo);
        }
#pragma unroll
        for (int kk = 0; kk < 4; ++kk) {
            const int cur = kk & 1, nxt = cur ^ 1;
            if (kk < 3) {   // prefetch kk+1 fragments
                const uint32_t ao = (uint32_t)(((2 * (kk + 1) + hiA) ^ sx) << 4);
                const uint32_t bo = (uint32_t)(((2 * (kk + 1) + hiB) ^ sx) << 4);
                ldsm4(a[nxt][0], Ab + aRow0 + ao);
                ldsm4(a[nxt][1], Ab + aRow1 + ao);
                ldsm4(b1f[nxt][0], B1b + bRow0 + bo);
                ldsm4(b1f[nxt][1], B1b + bRow1 + bo);
                ldsm4(b3f[nxt][0], B3b + bRow0 + bo);
                ldsm4(b3f[nxt][1], B3b + bRow1 + bo);
            }
#pragma unroll
            for (int im = 0; im < 2; ++im)
#pragma unroll
                for (int j = 0; j < 4; ++j) {
                    mma16816(acc1[im][j], a[cur][im],
                             b1f[cur][j >> 1][(j & 1) * 2], b1f[cur][j >> 1][(j & 1) * 2 + 1]);
                    mma16816(acc3[im][j], a[cur][im],
                             b3f[cur][j >> 1][(j & 1) * 2], b3f[cur][j >> 1][(j & 1) * 2 + 1]);
                }
        }
    };

    const int NK = D_DIM / KSTAGE;   // 16
    load_stage(0, 0);
    load_stage(1, 1);
    load_stage(2, 2);
    for (int kt = 0; kt < NK; ++kt) {
        if (kt < NK - 2)       cp_wait<2>();
        else if (kt == NK - 2) cp_wait<1>();
        else                   cp_wait<0>();
        __syncthreads();
        if (kt + 3 < NK) load_stage((kt + 3) & (NBUF - 1), kt + 3);
        compute_stage(kt & (NBUF - 1));
    }

    const int mbase = mtile * 128 + wm * 32 + (lane >> 2);
    const int fbase = ntile * 64 + wn * 32 + (lane & 3) * 2;
#pragma unroll
    for (int im = 0; im < 2; ++im)
#pragma unroll
        for (int j = 0; j < 4; ++j)
#pragma unroll
            for (int hh = 0; hh < 2; ++hh) {
                int m = mbase + im * 16 + hh * 8;
                if (m < cnt) {
                    float v0 = siluf(acc1[im][j][hh * 2])     * acc3[im][j][hh * 2];
                    float v1 = siluf(acc1[im][j][hh * 2 + 1]) * acc3[im][j][hh * 2 + 1];
                    *reinterpret_cast<__nv_bfloat162*>(
                        &g_h[(size_t)(off + m) * F_DIM + fbase + j * 8]) =
                        __floats2bfloat162_rn(v0, v1);
                }
            }
}

// ---------------- kernel 6: GEMM2 (h @ w2^T -> ys) ----------------
// CTA tile: M=128, N=128. 8 warps (4m x 2n), warp tile 32x64. Reg-double-buffered frags.
__global__ void __launch_bounds__(256) gemm2_kernel() {
    extern __shared__ __align__(128) char smem[];
    const int e = blockIdx.z;
    const int cnt = g_cnt[e];
    const int mtile = blockIdx.y;
    if (mtile * 128 >= cnt) return;
    const int ntile = blockIdx.x;     // 0..7
    const int off = g_off[e];
    const int tid = threadIdx.x;
    const int lane = tid & 31;
    const int w = tid >> 5;
    const int wm = w & 3, wn = w >> 2;

    int* rowsA = (int*)smem;
    const uint32_t sb = (uint32_t)__cvta_generic_to_shared(smem);
    const uint32_t dataB = sb + 1024;

    if (tid < 128) {
        int m = mtile * 128 + tid;
        rowsA[tid] = off + (m < cnt ? m : cnt - 1);
    }
    __syncthreads();

    const __nv_bfloat16* w2p = g_w2b + ((size_t)e * D_DIM + (size_t)ntile * 128) * F_DIM;

    const int rr = tid >> 3;
    const int cc = tid & 7;
    const uint32_t swoff = (uint32_t)cc << 4;

    auto load_stage = [&](int buf, int kt) {
        const uint32_t base = dataB + (uint32_t)buf * G2_STAGE;
        const int k0 = kt * KSTAGE;
#pragma unroll
        for (int p = 0; p < 4; ++p) {            // A: 128 rows of h
            int r = p * 32 + rr;
            uint32_t so = (uint32_t)(r << 7) + (swoff ^ ((uint32_t)(r & 7) << 4));
            cp16s(base + so, g_h + (size_t)rowsA[r] * F_DIM + k0 + cc * 8);
        }
#pragma unroll
        for (int p = 0; p < 4; ++p) {            // B: 128 rows of w2
            int r = p * 32 + rr;
            uint32_t so = (uint32_t)(r << 7) + (swoff ^ ((uint32_t)(r & 7) << 4));
            cp16s(base + 16384 + so, w2p + (size_t)r * F_DIM + k0 + cc * 8);
        }
        cp_commit();
    };

    float acc[2][8][4];
#pragma unroll
    for (int a = 0; a < 2; ++a)
#pragma unroll
        for (int b = 0; b < 8; ++b)
#pragma unroll
            for (int c = 0; c < 4; ++c) acc[a][b][c] = 0.f;

    const int sx  = lane & 7;
    const int hiA = lane >> 4;
    const int rA  = wm * 32 + (lane & 15);
    const int hiB = (lane >> 3) & 1;
    const int rB  = wn * 64 + ((lane >> 4) & 1) * 8 + (lane & 7);
    const uint32_t aRow0 = (uint32_t)(rA << 7), aRow1 = (uint32_t)((rA + 16) << 7);
    uint32_t bRow[4];
#pragma unroll
    for (int i = 0; i < 4; ++i) bRow[i] = (uint32_t)((rB + i * 16) << 7);

    auto compute_stage = [&](int buf) {
        const uint32_t base = dataB + (uint32_t)buf * G2_STAGE;
        const uint32_t Ab = base, Bb = base + 16384;
        uint32_t a[2][2][4], bf[2][4][4];
        {   // preload kk=0
            const uint32_t ao = (uint32_t)((hiA ^ sx) << 4);
            const uint32_t bo = (uint32_t)((hiB ^ sx) << 4);
            ldsm4(a[0][0], Ab + aRow0 + ao);
            ldsm4(a[0][1], Ab + aRow1 + ao);
#pragma unroll
            for (int i16 = 0; i16 < 4; ++i16)
                ldsm4(bf[0][i16], Bb + bRow[i16] + bo);
        }
#pragma unroll
        for (int kk = 0; kk < 4; ++kk) {
            const int cur = kk & 1, nxt = cur ^ 1;
            if (kk < 3) {
                const uint32_t ao = (uint32_t)(((2 * (kk + 1) + hiA) ^ sx) << 4);
                const uint32_t bo = (uint32_t)(((2 * (kk + 1) + hiB) ^ sx) << 4);
                ldsm4(a[nxt][0], Ab + aRow0 + ao);
                ldsm4(a[nxt][1], Ab + aRow1 + ao);
#pragma unroll
                for (int i16 = 0; i16 < 4; ++i16)
                    ldsm4(bf[nxt][i16], Bb + bRow[i16] + bo);
            }
#pragma unroll
            for (int im = 0; im < 2; ++im)
#pragma unroll
                for (int j = 0; j < 8; ++j)
                    mma16816(acc[im][j], a[cur][im],
                             bf[cur][j >> 1][(j & 1) * 2], bf[cur][j >> 1][(j & 1) * 2 + 1]);
        }
    };

    const int NK = F_DIM / KSTAGE;   // 64
    load_stage(0, 0);
    load_stage(1, 1);
    load_stage(2, 2);
    for (int kt = 0; kt < NK; ++kt) {
        if (kt < NK - 2)       cp_wait<2>();
        else if (kt == NK - 2) cp_wait<1>();
        else                   cp_wait<0>();
        __syncthreads();
        if (kt + 3 < NK) load_stage((kt + 3) & (NBUF - 1), kt + 3);
        compute_stage(kt & (NBUF - 1));
    }

    const int mbase = mtile * 128 + wm * 32 + (lane >> 2);
    const int dbase = ntile * 128 + wn * 64 + (lane & 3) * 2;
#pragma unroll
    for (int im = 0; im < 2; ++im)
#pragma unroll
        for (int j = 0; j < 8; ++j)
#pragma unroll
            for (int hh = 0; hh < 2; ++hh) {
                int m = mbase + im * 16 + hh * 8;
                if (m < cnt) {
                    float2 v;
                    v.x = acc[im][j][hh * 2];
                    v.y = acc[im][j][hh * 2 + 1];
                    *reinterpret_cast<float2*>(
                        &g_ys[(size_t)(off + m) * D_DIM + dbase + j * 8]) = v;
                }
            }
}

// ---------------- kernel 7: combine (residual + weighted expert outputs) ----------------
__global__ void __launch_bounds__(256) combine_kernel(const float* __restrict__ x,
                                                      float* __restrict__ out) {
    const int t = blockIdx.x;
    const int s0 = g_slot[2 * t], s1 = g_slot[2 * t + 1];
    const float g0 = g_gw[2 * t], g1 = g_gw[2 * t + 1];
    const int d = threadIdx.x * 4;
    float4 xv = *reinterpret_cast<const float4*>(x + (size_t)t * D_DIM + d);
    float4 y0 = *reinterpret_cast<const float4*>(g_ys + (size_t)s0 * D_DIM + d);
    float4 y1 = *reinterpret_cast<const float4*>(g_ys + (size_t)s1 * D_DIM + d);
    float4 o;
    o.x = xv.x + g0 * y0.x + g1 * y1.x;
    o.y = xv.y + g0 * y0.y + g1 * y1.y;
    o.z = xv.z + g0 * y0.z + g1 * y1.z;
    o.w = xv.w + g0 * y0.w + g1 * y1.w;
    *reinterpret_cast<float4*>(out + (size_t)t * D_DIM + d) = o;
}

// ---------------- launch ----------------
extern "C" void kernel_launch(void* const* d_in, const int* in_sizes, int n_in,
                              void* d_out, int out_size) {
    (void)in_sizes; (void)n_in; (void)out_size;
    const float* x      = (const float*)d_in[0];
    const float* gate_w = (const float*)d_in[1];
    const float* ln_w   = (const float*)d_in[2];
    const float* w1     = (const float*)d_in[3];
    const float* w3     = (const float*)d_in[4];
    const float* w2     = (const float*)d_in[5];
    float* out = (float*)d_out;

    cudaFuncSetAttribute(gemm1_kernel, cudaFuncAttributeMaxDynamicSharedMemorySize, G1_SMEM);
    cudaFuncSetAttribute(gemm2_kernel, cudaFuncAttributeMaxDynamicSharedMemorySize, G2_SMEM);

    zero_kernel<<<1, 32>>>();                                          // 0
    gate_kernel<<<T_TOK / 8, 256>>>(x, gate_w);                        // 1
    scan_kernel<<<1, 1>>>();                                           // 2
    scatter_kernel<<<(T_TOK + 255) / 256, 256>>>();                    // 3
    conv_all_kernel<<<dim3((E_EXP * F_DIM * D_DIM) / 4 / 256, 2), 256>>>(w1, w3, w2, ln_w); // 4
    gemm1_kernel<<<dim3(F_DIM / 64, T_TOK / 128, E_EXP), 256, G1_SMEM>>>();  // 5 <- ncu -s 5
    gemm2_kernel<<<dim3(D_DIM / 128, T_TOK / 128, E_EXP), 256, G2_SMEM>>>(); // 6
    combine_kernel<<<T_TOK, 256>>>(x, out);                            // 7
}

// round 7
// speedup vs baseline: 1.7040x; 1.2666x over previous
#include <cuda_runtime.h>
#include <cuda_bf16.h>
#include <stdint.h>

#define E_EXP 8
#define D_DIM 1024
#define F_DIM 4096
#define T_TOK 4096
#define NSLOT (T_TOK * 2)

// ---------------- scratch (static __device__ arrays; no allocation) ----------------
__device__ __nv_bfloat16 g_xnb[(size_t)T_TOK * D_DIM];          // normalized x, bf16
__device__ __nv_bfloat16 g_w1b[(size_t)E_EXP * F_DIM * D_DIM];  // bf16(w1 * ln_w)
__device__ __nv_bfloat16 g_w3b[(size_t)E_EXP * F_DIM * D_DIM];  // bf16(w3 * ln_w)
__device__ __nv_bfloat16 g_w2b[(size_t)E_EXP * D_DIM * F_DIM];  // bf16(w2)
__device__ __nv_bfloat16 g_h[(size_t)NSLOT * F_DIM];            // gated activations
__device__ float         g_ys[(size_t)NSLOT * D_DIM];           // per-slot FFN output
__device__ int   g_cnt[E_EXP];     // zero-initialized at load; re-zeroed by combine each call
__device__ int   g_off[E_EXP];
__device__ int   g_perm[NSLOT];
__device__ int   g_tokE[NSLOT];
__device__ int   g_slot[NSLOT];
__device__ float g_gw[NSLOT];

// ---------------- small helpers ----------------
__device__ __forceinline__ void cp16s(uint32_t dst, const void* src) {
    asm volatile("cp.async.cg.shared.global [%0], [%1], 16;\n" :: "r"(dst), "l"(src));
}
__device__ __forceinline__ void cp_commit() { asm volatile("cp.async.commit_group;\n" ::: "memory"); }
template <int N>
__device__ __forceinline__ void cp_wait() { asm volatile("cp.async.wait_group %0;\n" :: "n"(N) : "memory"); }

__device__ __forceinline__ void ldsm4(uint32_t* r, uint32_t a) {
    asm volatile("ldmatrix.sync.aligned.m8n8.x4.shared.b16 {%0,%1,%2,%3}, [%4];\n"
                 : "=r"(r[0]), "=r"(r[1]), "=r"(r[2]), "=r"(r[3]) : "r"(a));
}
__device__ __forceinline__ void mma16816(float* c, const uint32_t* a, uint32_t b0, uint32_t b1) {
    asm volatile(
        "mma.sync.aligned.m16n8k16.row.col.f32.bf16.bf16.f32 "
        "{%0,%1,%2,%3}, {%4,%5,%6,%7}, {%8,%9}, {%0,%1,%2,%3};\n"
        : "+f"(c[0]), "+f"(c[1]), "+f"(c[2]), "+f"(c[3])
        : "r"(a[0]), "r"(a[1]), "r"(a[2]), "r"(a[3]), "r"(b0), "r"(b1));
}
__device__ __forceinline__ float siluf(float v) { return v / (1.f + __expf(-v)); }

// ---------------- kernel 0: gating + rmsnorm (one warp per token) ----------------
// g_cnt must be zero on entry: static-init zero on first call, re-zeroed by combine_kernel.
__global__ void __launch_bounds__(256) gate_kernel(const float* __restrict__ x,
                                                   const float* __restrict__ gw) {
    const int wid = threadIdx.x >> 5, lane = threadIdx.x & 31;
    const int t = blockIdx.x * 8 + wid;
    float xr[32];
    float ss = 0.f;
    const float* xp = x + (size_t)t * D_DIM + lane;
#pragma unroll
    for (int i = 0; i < 32; ++i) { xr[i] = xp[i * 32]; ss += xr[i] * xr[i]; }
    float sc[8];
#pragma unroll
    for (int e = 0; e < 8; ++e) {
        const float* gp = gw + e * D_DIM + lane;
        float s = 0.f;
#pragma unroll
        for (int i = 0; i < 32; ++i) s += xr[i] * gp[i * 32];
        sc[e] = s;
    }
#pragma unroll
    for (int o = 16; o > 0; o >>= 1) {
        ss += __shfl_xor_sync(0xffffffffu, ss, o);
#pragma unroll
        for (int e = 0; e < 8; ++e) sc[e] += __shfl_xor_sync(0xffffffffu, sc[e], o);
    }
    const float inv = rsqrtf(ss * (1.f / D_DIM) + 1e-6f);
    __nv_bfloat16* xo = g_xnb + (size_t)t * D_DIM + lane;
#pragma unroll
    for (int i = 0; i < 32; ++i) xo[i * 32] = __float2bfloat16(xr[i] * inv);

    if (lane == 0) {
        int i0 = 0; float v0 = sc[0];
#pragma unroll
        for (int e = 1; e < 8; ++e) if (sc[e] > v0) { v0 = sc[e]; i0 = e; }
        int i1 = (i0 == 0) ? 1 : 0; float v1 = sc[i1];
#pragma unroll
        for (int e = 0; e < 8; ++e)
            if (e != i0 && sc[e] > v1) { v1 = sc[e]; i1 = e; }
        const float e1 = __expf(v1 - v0);
        const float z  = 1.f + e1;
        g_tokE[2 * t] = i0; g_tokE[2 * t + 1] = i1;
        g_gw[2 * t] = 1.f / z; g_gw[2 * t + 1] = e1 / z;
        atomicAdd(&g_cnt[i0], 1);
        atomicAdd(&g_cnt[i1], 1);
    }
}

// ---------------- kernel 1: scan + scatter (single block) ----------------
__global__ void __launch_bounds__(1024) scan_scatter_kernel() {
    __shared__ int s_cur[E_EXP];
    const int tid = threadIdx.x;
    if (tid == 0) {
        int s = 0;
        for (int e = 0; e < E_EXP; ++e) { g_off[e] = s; s_cur[e] = s; s += g_cnt[e]; }
    }
    __syncthreads();
    for (int t = tid; t < T_TOK; t += 1024) {
#pragma unroll
        for (int k = 0; k < 2; ++k) {
            int e = g_tokE[2 * t + k];
            int s = atomicAdd(&s_cur[e], 1);
            g_perm[s] = t;
            g_slot[2 * t + k] = s;
        }
    }
}

// ---------------- kernel 2: weight conversion fp32 -> bf16 (fold ln into w1/w3) ----
// Blocks iterate in REVERSE so expert 0 (first consumed by gemm1) is converted last (L2-hot).
__global__ void __launch_bounds__(256) conv_all_kernel(const float* __restrict__ w1,
                                                       const float* __restrict__ w3,
                                                       const float* __restrict__ w2,
                                                       const float* __restrict__ ln) {
    size_t i = ((size_t)(gridDim.x - 1 - blockIdx.x) * 256 + threadIdx.x) * 4;
    if (blockIdx.y == 0) {
        int e = (int)(i >> 22);          // F*D = 2^22
        int d = (int)(i & (D_DIM - 1));
        float4 l = *reinterpret_cast<const float4*>(ln + (size_t)e * D_DIM + d);
        float4 a = *reinterpret_cast<const float4*>(w1 + i);
        float4 b = *reinterpret_cast<const float4*>(w3 + i);
        __nv_bfloat162* o1 = reinterpret_cast<__nv_bfloat162*>(g_w1b + i);
        __nv_bfloat162* o3 = reinterpret_cast<__nv_bfloat162*>(g_w3b + i);
        o1[0] = __floats2bfloat162_rn(a.x * l.x, a.y * l.y);
        o1[1] = __floats2bfloat162_rn(a.z * l.z, a.w * l.w);
        o3[0] = __floats2bfloat162_rn(b.x * l.x, b.y * l.y);
        o3[1] = __floats2bfloat162_rn(b.z * l.z, b.w * l.w);
    } else {
        float4 a = *reinterpret_cast<const float4*>(w2 + i);
        __nv_bfloat162* o = reinterpret_cast<__nv_bfloat162*>(g_w2b + i);
        o[0] = __floats2bfloat162_rn(a.x, a.y);
        o[1] = __floats2bfloat162_rn(a.z, a.w);
    }
}

// ================= GEMM settings =================
// K-stage = 64, NBUF = 2 (66.5 KB smem) -> 2 CTAs/SM. Regs capped at 128.
#define KSTAGE 64
#define NBUF   2
#define G_STAGE 32768
#define G_SMEM  (1024 + NBUF * G_STAGE)

// ---------------- kernel 3: GEMM1 (xn @ w1^T, xn @ w3^T, fused silu-gate) ----------------
// CTA tile: M=128, N=64 per matrix. 8 warps (4m x 2n), warp tile 32x32 per matrix.
__global__ void __launch_bounds__(256, 2) gemm1_kernel() {
    extern __shared__ __align__(128) char smem[];
    const int e = blockIdx.z;
    const int cnt = g_cnt[e];
    const int mtile = blockIdx.y;
    if (mtile * 128 >= cnt) return;
    const int ntile = blockIdx.x;
    const int off = g_off[e];
    const int tid = threadIdx.x;
    const int lane = tid & 31;
    const int w = tid >> 5;
    const int wm = w & 3, wn = w >> 2;

    int* rows = (int*)smem;
    const uint32_t sb = (uint32_t)__cvta_generic_to_shared(smem);
    const uint32_t dataB = sb + 1024;

    if (tid < 128) {
        int m = mtile * 128 + tid;
        rows[tid] = g_perm[off + (m < cnt ? m : cnt - 1)];
    }
    __syncthreads();

    const __nv_bfloat16* w1p = g_w1b + ((size_t)e * F_DIM + (size_t)ntile * 64) * D_DIM;
    const __nv_bfloat16* w3p = g_w3b + ((size_t)e * F_DIM + (size_t)ntile * 64) * D_DIM;

    const int rr = tid >> 3;    // row group
    const int cc = tid & 7;     // 16B chunk
    const uint32_t swoff = (uint32_t)cc << 4;

    auto load_stage = [&](int buf, int kt) {
        const uint32_t base = dataB + (uint32_t)buf * G_STAGE;
        const int k0 = kt * KSTAGE;
#pragma unroll
        for (int p = 0; p < 4; ++p) {            // A: 128 rows
            int r = p * 32 + rr;
            uint32_t dst = base + (uint32_t)(r << 7) + (swoff ^ ((uint32_t)(r & 7) << 4));
            cp16s(dst, g_xnb + (size_t)rows[r] * D_DIM + k0 + cc * 8);
        }
#pragma unroll
        for (int p = 0; p < 2; ++p) {            // B1, B3: 64 rows each
            int r = p * 32 + rr;
            uint32_t so = (uint32_t)(r << 7) + (swoff ^ ((uint32_t)(r & 7) << 4));
            cp16s(base + 16384 + so, w1p + (size_t)r * D_DIM + k0 + cc * 8);
            cp16s(base + 24576 + so, w3p + (size_t)r * D_DIM + k0 + cc * 8);
        }
        cp_commit();
    };

    float acc1[2][4][4], acc3[2][4][4];
#pragma unroll
    for (int a = 0; a < 2; ++a)
#pragma unroll
        for (int b = 0; b < 4; ++b)
#pragma unroll
            for (int c = 0; c < 4; ++c) { acc1[a][b][c] = 0.f; acc3[a][b][c] = 0.f; }

    const int sx  = lane & 7;
    const int hiA = lane >> 4;
    const int rA  = wm * 32 + (lane & 15);
    const int hiB = (lane >> 3) & 1;
    const int rB  = wn * 32 + ((lane >> 4) & 1) * 8 + (lane & 7);
    const uint32_t aRow0 = (uint32_t)(rA << 7), aRow1 = (uint32_t)((rA + 16) << 7);
    const uint32_t bRow0 = (uint32_t)(rB << 7), bRow1 = (uint32_t)((rB + 16) << 7);

    auto compute_stage = [&](int buf) {
        const uint32_t base = dataB + (uint32_t)buf * G_STAGE;
        const uint32_t Ab = base, B1b = base + 16384, B3b = base + 24576;
#pragma unroll
        for (int kk = 0; kk < 4; ++kk) {
            const uint32_t ao = (uint32_t)(((2 * kk + hiA) ^ sx) << 4);
            const uint32_t bo = (uint32_t)(((2 * kk + hiB) ^ sx) << 4);
            uint32_t a[2][4];
            ldsm4(a[0], Ab + aRow0 + ao);
            ldsm4(a[1], Ab + aRow1 + ao);
            uint32_t b1f[2][4], b3f[2][4];
            ldsm4(b1f[0], B1b + bRow0 + bo);
            ldsm4(b1f[1], B1b + bRow1 + bo);
            ldsm4(b3f[0], B3b + bRow0 + bo);
            ldsm4(b3f[1], B3b + bRow1 + bo);
#pragma unroll
            for (int im = 0; im < 2; ++im)
#pragma unroll
                for (int j = 0; j < 4; ++j) {
                    mma16816(acc1[im][j], a[im],
                             b1f[j >> 1][(j & 1) * 2], b1f[j >> 1][(j & 1) * 2 + 1]);
                    mma16816(acc3[im][j], a[im],
                             b3f[j >> 1][(j & 1) * 2], b3f[j >> 1][(j & 1) * 2 + 1]);
                }
        }
    };

    const int NK = D_DIM / KSTAGE;   // 16
    load_stage(0, 0);
    for (int kt = 0; kt < NK; ++kt) {
        cp_wait<0>();
        __syncthreads();
        if (kt + 1 < NK) load_stage((kt + 1) & 1, kt + 1);
        compute_stage(kt & 1);
    }

    const int mbase = mtile * 128 + wm * 32 + (lane >> 2);
    const int fbase = ntile * 64 + wn * 32 + (lane & 3) * 2;
#pragma unroll
    for (int im = 0; im < 2; ++im)
#pragma unroll
        for (int j = 0; j < 4; ++j)
#pragma unroll
            for (int hh = 0; hh < 2; ++hh) {
                int m = mbase + im * 16 + hh * 8;
                if (m < cnt) {
                    float v0 = siluf(acc1[im][j][hh * 2])     * acc3[im][j][hh * 2];
                    float v1 = siluf(acc1[im][j][hh * 2 + 1]) * acc3[im][j][hh * 2 + 1];
                    *reinterpret_cast<__nv_bfloat162*>(
                        &g_h[(size_t)(off + m) * F_DIM + fbase + j * 8]) =
                        __floats2bfloat162_rn(v0, v1);
                }
            }
}

// ---------------- kernel 4: GEMM2 (h @ w2^T -> ys) ----------------
// CTA tile: M=128, N=128. 8 warps (4m x 2n), warp tile 32x64.
// Experts processed in REVERSE order (expert 7's g_h freshest in L2 from gemm1).
__global__ void __launch_bounds__(256, 2) gemm2_kernel() {
    extern __shared__ __align__(128) char smem[];
    const int e = E_EXP - 1 - blockIdx.z;
    const int cnt = g_cnt[e];
    const int mtile = blockIdx.y;
    if (mtile * 128 >= cnt) return;
    const int ntile = blockIdx.x;     // 0..7
    const int off = g_off[e];
    const int tid = threadIdx.x;
    const int lane = tid & 31;
    const int w = tid >> 5;
    const int wm = w & 3, wn = w >> 2;

    int* rowsA = (int*)smem;
    const uint32_t sb = (uint32_t)__cvta_generic_to_shared(smem);
    const uint32_t dataB = sb + 1024;

    if (tid < 128) {
        int m = mtile * 128 + tid;
        rowsA[tid] = off + (m < cnt ? m : cnt - 1);
    }
    __syncthreads();

    const __nv_bfloat16* w2p = g_w2b + ((size_t)e * D_DIM + (size_t)ntile * 128) * F_DIM;

    const int rr = tid >> 3;
    const int cc = tid & 7;
    const uint32_t swoff = (uint32_t)cc << 4;

    auto load_stage = [&](int buf, int kt) {
        const uint32_t base = dataB + (uint32_t)buf * G_STAGE;
        const int k0 = kt * KSTAGE;
#pragma unroll
        for (int p = 0; p < 4; ++p) {            // A: 128 rows of h
            int r = p * 32 + rr;
            uint32_t so = (uint32_t)(r << 7) + (swoff ^ ((uint32_t)(r & 7) << 4));
            cp16s(base + so, g_h + (size_t)rowsA[r] * F_DIM + k0 + cc * 8);
        }
#pragma unroll
        for (int p = 0; p < 4; ++p) {            // B: 128 rows of w2
            int r = p * 32 + rr;
            uint32_t so = (uint32_t)(r << 7) + (swoff ^ ((uint32_t)(r & 7) << 4));
            cp16s(base + 16384 + so, w2p + (size_t)r * F_DIM + k0 + cc * 8);
        }
        cp_commit();
    };

    float acc[2][8][4];
#pragma unroll
    for (int a = 0; a < 2; ++a)
#pragma unroll
        for (int b = 0; b < 8; ++b)
#pragma unroll
            for (int c = 0; c < 4; ++c) acc[a][b][c] = 0.f;

    const int sx  = lane & 7;
    const int hiA = lane >> 4;
    const int rA  = wm * 32 + (lane & 15);
    const int hiB = (lane >> 3) & 1;
    const int rB  = wn * 64 + ((lane >> 4) & 1) * 8 + (lane & 7);
    const uint32_t aRow0 = (uint32_t)(rA << 7), aRow1 = (uint32_t)((rA + 16) << 7);
    uint32_t bRow[4];
#pragma unroll
    for (int i = 0; i < 4; ++i) bRow[i] = (uint32_t)((rB + i * 16) << 7);

    auto compute_stage = [&](int buf) {
        const uint32_t base = dataB + (uint32_t)buf * G_STAGE;
        const uint32_t Ab = base, Bb = base + 16384;
#pragma unroll
        for (int kk = 0; kk < 4; ++kk) {
            const uint32_t ao = (uint32_t)(((2 * kk + hiA) ^ sx) << 4);
            const uint32_t bo = (uint32_t)(((2 * kk + hiB) ^ sx) << 4);
            uint32_t a[2][4];
            ldsm4(a[0], Ab + aRow0 + ao);
            ldsm4(a[1], Ab + aRow1 + ao);
            uint32_t bf[4][4];
#pragma unroll
            for (int i16 = 0; i16 < 4; ++i16)
                ldsm4(bf[i16], Bb + bRow[i16] + bo);
#pragma unroll
            for (int im = 0; im < 2; ++im)
#pragma unroll
                for (int j = 0; j < 8; ++j)
                    mma16816(acc[im][j], a[im],
                             bf[j >> 1][(j & 1) * 2], bf[j >> 1][(j & 1) * 2 + 1]);
        }
    };

    const int NK = F_DIM / KSTAGE;   // 64
    load_stage(0, 0);
    for (int kt = 0; kt < NK; ++kt) {
        cp_wait<0>();
        __syncthreads();
        if (kt + 1 < NK) load_stage((kt + 1) & 1, kt + 1);
        compute_stage(kt & 1);
    }

    const int mbase = mtile * 128 + wm * 32 + (lane >> 2);
    const int dbase = ntile * 128 + wn * 64 + (lane & 3) * 2;
#pragma unroll
    for (int im = 0; im < 2; ++im)
#pragma unroll
        for (int j = 0; j < 8; ++j)
#pragma unroll
            for (int hh = 0; hh < 2; ++hh) {
                int m = mbase + im * 16 + hh * 8;
                if (m < cnt) {
                    float2 v;
                    v.x = acc[im][j][hh * 2];
                    v.y = acc[im][j][hh * 2 + 1];
                    *reinterpret_cast<float2*>(
                        &g_ys[(size_t)(off + m) * D_DIM + dbase + j * 8]) = v;
                }
            }
}

// ---------------- kernel 5: combine (residual + weighted expert outputs) + counter reset ----
__global__ void __launch_bounds__(256) combine_kernel(const float* __restrict__ x,
                                                      float* __restrict__ out) {
    const int t = blockIdx.x;
    if (blockIdx.x == 0 && threadIdx.x < E_EXP) g_cnt[threadIdx.x] = 0;  // reset for next call
    const int s0 = g_slot[2 * t], s1 = g_slot[2 * t + 1];
    const float g0 = g_gw[2 * t], g1 = g_gw[2 * t + 1];
    const int d = threadIdx.x * 4;
    float4 xv = *reinterpret_cast<const float4*>(x + (size_t)t * D_DIM + d);
    float4 y0 = *reinterpret_cast<const float4*>(g_ys + (size_t)s0 * D_DIM + d);
    float4 y1 = *reinterpret_cast<const float4*>(g_ys + (size_t)s1 * D_DIM + d);
    float4 o;
    o.x = xv.x + g0 * y0.x + g1 * y1.x;
    o.y = xv.y + g0 * y0.y + g1 * y1.y;
    o.z = xv.z + g0 * y0.z + g1 * y1.z;
    o.w = xv.w + g0 * y0.w + g1 * y1.w;
    *reinterpret_cast<float4*>(out + (size_t)t * D_DIM + d) = o;
}

// ---------------- launch ----------------
extern "C" void kernel_launch(void* const* d_in, const int* in_sizes, int n_in,
                              void* d_out, int out_size) {
    (void)in_sizes; (void)n_in; (void)out_size;
    const float* x      = (const float*)d_in[0];
    const float* gate_w = (const float*)d_in[1];
    const float* ln_w   = (const float*)d_in[2];
    const float* w1     = (const float*)d_in[3];
    const float* w3     = (const float*)d_in[4];
    const float* w2     = (const float*)d_in[5];
    float* out = (float*)d_out;

    cudaFuncSetAttribute(gemm1_kernel, cudaFuncAttributeMaxDynamicSharedMemorySize, G_SMEM);
    cudaFuncSetAttribute(gemm2_kernel, cudaFuncAttributeMaxDynamicSharedMemorySize, G_SMEM);

    gate_kernel<<<T_TOK / 8, 256>>>(x, gate_w);                                   // 0
    scan_scatter_kernel<<<1, 1024>>>();                                           // 1
    conv_all_kernel<<<dim3((E_EXP * F_DIM * D_DIM) / 4 / 256, 2), 256>>>(w1, w3, w2, ln_w); // 2
    gemm1_kernel<<<dim3(F_DIM / 64, T_TOK / 128, E_EXP), 256, G_SMEM>>>();        // 3
    gemm2_kernel<<<dim3(D_DIM / 128, T_TOK / 128, E_EXP), 256, G_SMEM>>>();       // 4
    combine_kernel<<<T_TOK, 256>>>(x, out);                                       // 5
}

// round 8
// speedup vs baseline: 1.7091x; 1.0030x over previous
#include <cuda_runtime.h>
#include <cuda_bf16.h>
#include <stdint.h>

#define E_EXP 8
#define D_DIM 1024
#define F_DIM 4096
#define T_TOK 4096
#define NSLOT (T_TOK * 2)

// ---------------- scratch (static __device__ arrays; no allocation) ----------------
__device__ __nv_bfloat16 g_xnb[(size_t)T_TOK * D_DIM];          // normalized x, bf16
__device__ __nv_bfloat16 g_w1b[(size_t)E_EXP * F_DIM * D_DIM];  // bf16(w1 * ln_w)
__device__ __nv_bfloat16 g_w3b[(size_t)E_EXP * F_DIM * D_DIM];  // bf16(w3 * ln_w)
__device__ __nv_bfloat16 g_w2b[(size_t)E_EXP * D_DIM * F_DIM];  // bf16(w2)
__device__ __nv_bfloat16 g_h[(size_t)NSLOT * F_DIM];            // gated activations
__device__ float         g_ys[(size_t)NSLOT * D_DIM];           // per-slot FFN output
__device__ int   g_cnt[E_EXP];     // zero at load; re-zeroed by combine each call
__device__ int   g_off[E_EXP];
__device__ int   g_perm[NSLOT];
__device__ int   g_tokE[NSLOT];
__device__ int   g_slot[NSLOT];
__device__ float g_gw[NSLOT];

// ---------------- small helpers ----------------
__device__ __forceinline__ void cp16s(uint32_t dst, const void* src) {
    asm volatile("cp.async.cg.shared.global [%0], [%1], 16;\n" :: "r"(dst), "l"(src));
}
__device__ __forceinline__ void cp_commit() { asm volatile("cp.async.commit_group;\n" ::: "memory"); }
template <int N>
__device__ __forceinline__ void cp_wait() { asm volatile("cp.async.wait_group %0;\n" :: "n"(N) : "memory"); }

__device__ __forceinline__ void ldsm4(uint32_t* r, uint32_t a) {
    asm volatile("ldmatrix.sync.aligned.m8n8.x4.shared.b16 {%0,%1,%2,%3}, [%4];\n"
                 : "=r"(r[0]), "=r"(r[1]), "=r"(r[2]), "=r"(r[3]) : "r"(a));
}
__device__ __forceinline__ void mma16816(float* c, const uint32_t* a, uint32_t b0, uint32_t b1) {
    asm volatile(
        "mma.sync.aligned.m16n8k16.row.col.f32.bf16.bf16.f32 "
        "{%0,%1,%2,%3}, {%4,%5,%6,%7}, {%8,%9}, {%0,%1,%2,%3};\n"
        : "+f"(c[0]), "+f"(c[1]), "+f"(c[2]), "+f"(c[3])
        : "r"(a[0]), "r"(a[1]), "r"(a[2]), "r"(a[3]), "r"(b0), "r"(b1));
}
__device__ __forceinline__ float siluf(float v) { return v / (1.f + __expf(-v)); }

// ---------------- gating + rmsnorm (one warp per token) ----------------
__global__ void __launch_bounds__(256) gate_kernel(const float* __restrict__ x,
                                                   const float* __restrict__ gw) {
    const int wid = threadIdx.x >> 5, lane = threadIdx.x & 31;
    const int t = blockIdx.x * 8 + wid;
    float xr[32];
    float ss = 0.f;
    const float* xp = x + (size_t)t * D_DIM + lane;
#pragma unroll
    for (int i = 0; i < 32; ++i) { xr[i] = xp[i * 32]; ss += xr[i] * xr[i]; }
    float sc[8];
#pragma unroll
    for (int e = 0; e < 8; ++e) {
        const float* gp = gw + e * D_DIM + lane;
        float s = 0.f;
#pragma unroll
        for (int i = 0; i < 32; ++i) s += xr[i] * gp[i * 32];
        sc[e] = s;
    }
#pragma unroll
    for (int o = 16; o > 0; o >>= 1) {
        ss += __shfl_xor_sync(0xffffffffu, ss, o);
#pragma unroll
        for (int e = 0; e < 8; ++e) sc[e] += __shfl_xor_sync(0xffffffffu, sc[e], o);
    }
    const float inv = rsqrtf(ss * (1.f / D_DIM) + 1e-6f);
    __nv_bfloat16* xo = g_xnb + (size_t)t * D_DIM + lane;
#pragma unroll
    for (int i = 0; i < 32; ++i) xo[i * 32] = __float2bfloat16(xr[i] * inv);

    if (lane == 0) {
        int i0 = 0; float v0 = sc[0];
#pragma unroll
        for (int e = 1; e < 8; ++e) if (sc[e] > v0) { v0 = sc[e]; i0 = e; }
        int i1 = (i0 == 0) ? 1 : 0; float v1 = sc[i1];
#pragma unroll
        for (int e = 0; e < 8; ++e)
            if (e != i0 && sc[e] > v1) { v1 = sc[e]; i1 = e; }
        const float e1 = __expf(v1 - v0);
        const float z  = 1.f + e1;
        g_tokE[2 * t] = i0; g_tokE[2 * t + 1] = i1;
        g_gw[2 * t] = 1.f / z; g_gw[2 * t + 1] = e1 / z;
        atomicAdd(&g_cnt[i0], 1);
        atomicAdd(&g_cnt[i1], 1);
    }
}

// ---------------- scan + scatter (single block) ----------------
__global__ void __launch_bounds__(1024) scan_scatter_kernel() {
    __shared__ int s_cur[E_EXP];
    const int tid = threadIdx.x;
    if (tid == 0) {
        int s = 0;
        for (int e = 0; e < E_EXP; ++e) { g_off[e] = s; s_cur[e] = s; s += g_cnt[e]; }
    }
    __syncthreads();
    for (int t = tid; t < T_TOK; t += 1024) {
#pragma unroll
        for (int k = 0; k < 2; ++k) {
            int e = g_tokE[2 * t + k];
            int s = atomicAdd(&s_cur[e], 1);
            g_perm[s] = t;
            g_slot[2 * t + k] = s;
        }
    }
}

// ---------------- weight conversion fp32 -> bf16 (fold ln into w1/w3) ----------------
// Converts 4 experts per launch (ebase = 0 or 4).
__global__ void __launch_bounds__(256) conv13_kernel(const float* __restrict__ w1,
                                                     const float* __restrict__ w3,
                                                     const float* __restrict__ ln,
                                                     int ebase) {
    size_t i = ((size_t)ebase << 22) + ((size_t)blockIdx.x * 256 + threadIdx.x) * 4;
    int e = (int)(i >> 22);          // F*D = 2^22
    int d = (int)(i & (D_DIM - 1));
    float4 l = *reinterpret_cast<const float4*>(ln + (size_t)e * D_DIM + d);
    float4 a = *reinterpret_cast<const float4*>(w1 + i);
    float4 b = *reinterpret_cast<const float4*>(w3 + i);
    __nv_bfloat162* o1 = reinterpret_cast<__nv_bfloat162*>(g_w1b + i);
    __nv_bfloat162* o3 = reinterpret_cast<__nv_bfloat162*>(g_w3b + i);
    o1[0] = __floats2bfloat162_rn(a.x * l.x, a.y * l.y);
    o1[1] = __floats2bfloat162_rn(a.z * l.z, a.w * l.w);
    o3[0] = __floats2bfloat162_rn(b.x * l.x, b.y * l.y);
    o3[1] = __floats2bfloat162_rn(b.z * l.z, b.w * l.w);
}
__global__ void __launch_bounds__(256) conv2_kernel(const float* __restrict__ w2) {
    size_t i = ((size_t)blockIdx.x * 256 + threadIdx.x) * 4;
    float4 a = *reinterpret_cast<const float4*>(w2 + i);
    __nv_bfloat162* o = reinterpret_cast<__nv_bfloat162*>(g_w2b + i);
    o[0] = __floats2bfloat162_rn(a.x, a.y);
    o[1] = __floats2bfloat162_rn(a.z, a.w);
}

// ================= GEMM settings =================
// K-stage = 64, NBUF = 3 (97 KB smem) -> still 2 CTAs/SM (194 KB of 228 KB). Regs capped 128.
#define KSTAGE 64
#define NBUF   3
#define G_STAGE 32768
#define G_SMEM  (1024 + NBUF * G_STAGE)

// ---------------- GEMM1 (xn @ w1^T, xn @ w3^T, fused silu-gate) ----------------
// CTA tile: M=128, N=64 per matrix. 8 warps (4m x 2n). Covers 4 experts per launch.
__global__ void __launch_bounds__(256, 2) gemm1_kernel(int ebase) {
    extern __shared__ __align__(128) char smem[];
    const int e = ebase + blockIdx.z;
    const int cnt = g_cnt[e];
    const int mtile = blockIdx.y;
    if (mtile * 128 >= cnt) return;
    const int ntile = blockIdx.x;
    const int off = g_off[e];
    const int tid = threadIdx.x;
    const int lane = tid & 31;
    const int w = tid >> 5;
    const int wm = w & 3, wn = w >> 2;

    int* rows = (int*)smem;
    const uint32_t sb = (uint32_t)__cvta_generic_to_shared(smem);
    const uint32_t dataB = sb + 1024;

    if (tid < 128) {
        int m = mtile * 128 + tid;
        rows[tid] = g_perm[off + (m < cnt ? m : cnt - 1)];
    }
    __syncthreads();

    const __nv_bfloat16* w1p = g_w1b + ((size_t)e * F_DIM + (size_t)ntile * 64) * D_DIM;
    const __nv_bfloat16* w3p = g_w3b + ((size_t)e * F_DIM + (size_t)ntile * 64) * D_DIM;

    const int rr = tid >> 3;    // row group
    const int cc = tid & 7;     // 16B chunk
    const uint32_t swoff = (uint32_t)cc << 4;

    auto load_stage = [&](int buf, int kt) {
        const uint32_t base = dataB + (uint32_t)buf * G_STAGE;
        const int k0 = kt * KSTAGE;
#pragma unroll
        for (int p = 0; p < 4; ++p) {            // A: 128 rows
            int r = p * 32 + rr;
            uint32_t dst = base + (uint32_t)(r << 7) + (swoff ^ ((uint32_t)(r & 7) << 4));
            cp16s(dst, g_xnb + (size_t)rows[r] * D_DIM + k0 + cc * 8);
        }
#pragma unroll
        for (int p = 0; p < 2; ++p) {            // B1, B3: 64 rows each
            int r = p * 32 + rr;
            uint32_t so = (uint32_t)(r << 7) + (swoff ^ ((uint32_t)(r & 7) << 4));
            cp16s(base + 16384 + so, w1p + (size_t)r * D_DIM + k0 + cc * 8);
            cp16s(base + 24576 + so, w3p + (size_t)r * D_DIM + k0 + cc * 8);
        }
        cp_commit();
    };

    float acc1[2][4][4], acc3[2][4][4];
#pragma unroll
    for (int a = 0; a < 2; ++a)
#pragma unroll
        for (int b = 0; b < 4; ++b)
#pragma unroll
            for (int c = 0; c < 4; ++c) { acc1[a][b][c] = 0.f; acc3[a][b][c] = 0.f; }

    const int sx  = lane & 7;
    const int hiA = lane >> 4;
    const int rA  = wm * 32 + (lane & 15);
    const int hiB = (lane >> 3) & 1;
    const int rB  = wn * 32 + ((lane >> 4) & 1) * 8 + (lane & 7);
    const uint32_t aRow0 = (uint32_t)(rA << 7), aRow1 = (uint32_t)((rA + 16) << 7);
    const uint32_t bRow0 = (uint32_t)(rB << 7), bRow1 = (uint32_t)((rB + 16) << 7);

    auto compute_stage = [&](int buf) {
        const uint32_t base = dataB + (uint32_t)buf * G_STAGE;
        const uint32_t Ab = base, B1b = base + 16384, B3b = base + 24576;
#pragma unroll
        for (int kk = 0; kk < 4; ++kk) {
            const uint32_t ao = (uint32_t)(((2 * kk + hiA) ^ sx) << 4);
            const uint32_t bo = (uint32_t)(((2 * kk + hiB) ^ sx) << 4);
            uint32_t a[2][4];
            ldsm4(a[0], Ab + aRow0 + ao);
            ldsm4(a[1], Ab + aRow1 + ao);
            uint32_t b1f[2][4], b3f[2][4];
            ldsm4(b1f[0], B1b + bRow0 + bo);
            ldsm4(b1f[1], B1b + bRow1 + bo);
            ldsm4(b3f[0], B3b + bRow0 + bo);
            ldsm4(b3f[1], B3b + bRow1 + bo);
#pragma unroll
            for (int im = 0; im < 2; ++im)
#pragma unroll
                for (int j = 0; j < 4; ++j) {
                    mma16816(acc1[im][j], a[im],
                             b1f[j >> 1][(j & 1) * 2], b1f[j >> 1][(j & 1) * 2 + 1]);
                    mma16816(acc3[im][j], a[im],
                             b3f[j >> 1][(j & 1) * 2], b3f[j >> 1][(j & 1) * 2 + 1]);
                }
        }
    };

    const int NK = D_DIM / KSTAGE;   // 16
    load_stage(0, 0);
    load_stage(1, 1);
    int bc = 0, bl = 2;              // compute buf, load buf (mod 3)
    for (int kt = 0; kt < NK; ++kt) {
        if (kt < NK - 1) cp_wait<1>();
        else             cp_wait<0>();
        __syncthreads();
        if (kt + 2 < NK) {
            load_stage(bl, kt + 2);
            bl = (bl == 2) ? 0 : bl + 1;
        }
        compute_stage(bc);
        bc = (bc == 2) ? 0 : bc + 1;
    }

    const int mbase = mtile * 128 + wm * 32 + (lane >> 2);
    const int fbase = ntile * 64 + wn * 32 + (lane & 3) * 2;
#pragma unroll
    for (int im = 0; im < 2; ++im)
#pragma unroll
        for (int j = 0; j < 4; ++j)
#pragma unroll
            for (int hh = 0; hh < 2; ++hh) {
                int m = mbase + im * 16 + hh * 8;
                if (m < cnt) {
                    float v0 = siluf(acc1[im][j][hh * 2])     * acc3[im][j][hh * 2];
                    float v1 = siluf(acc1[im][j][hh * 2 + 1]) * acc3[im][j][hh * 2 + 1];
                    *reinterpret_cast<__nv_bfloat162*>(
                        &g_h[(size_t)(off + m) * F_DIM + fbase + j * 8]) =
                        __floats2bfloat162_rn(v0, v1);
                }
            }
}

// ---------------- GEMM2 (h @ w2^T -> ys) ----------------
// CTA tile: M=128, N=128. 8 warps (4m x 2n). Experts in REVERSE (expert 7 L2-hot).
__global__ void __launch_bounds__(256, 2) gemm2_kernel() {
    extern __shared__ __align__(128) char smem[];
    const int e = E_EXP - 1 - blockIdx.z;
    const int cnt = g_cnt[e];
    const int mtile = blockIdx.y;
    if (mtile * 128 >= cnt) return;
    const int ntile = blockIdx.x;     // 0..7
    const int off = g_off[e];
    const int tid = threadIdx.x;
    const int lane = tid & 31;
    const int w = tid >> 5;
    const int wm = w & 3, wn = w >> 2;

    int* rowsA = (int*)smem;
    const uint32_t sb = (uint32_t)__cvta_generic_to_shared(smem);
    const uint32_t dataB = sb + 1024;

    if (tid < 128) {
        int m = mtile * 128 + tid;
        rowsA[tid] = off + (m < cnt ? m : cnt - 1);
    }
    __syncthreads();

    const __nv_bfloat16* w2p = g_w2b + ((size_t)e * D_DIM + (size_t)ntile * 128) * F_DIM;

    const int rr = tid >> 3;
    const int cc = tid & 7;
    const uint32_t swoff = (uint32_t)cc << 4;

    auto load_stage = [&](int buf, int kt) {
        const uint32_t base = dataB + (uint32_t)buf * G_STAGE;
        const int k0 = kt * KSTAGE;
#pragma unroll
        for (int p = 0; p < 4; ++p) {            // A: 128 rows of h
            int r = p * 32 + rr;
            uint32_t so = (uint32_t)(r << 7) + (swoff ^ ((uint32_t)(r & 7) << 4));
            cp16s(base + so, g_h + (size_t)rowsA[r] * F_DIM + k0 + cc * 8);
        }
#pragma unroll
        for (int p = 0; p < 4; ++p) {            // B: 128 rows of w2
            int r = p * 32 + rr;
            uint32_t so = (uint32_t)(r << 7) + (swoff ^ ((uint32_t)(r & 7) << 4));
            cp16s(base + 16384 + so, w2p + (size_t)r * F_DIM + k0 + cc * 8);
        }
        cp_commit();
    };

    float acc[2][8][4];
#pragma unroll
    for (int a = 0; a < 2; ++a)
#pragma unroll
        for (int b = 0; b < 8; ++b)
#pragma unroll
            for (int c = 0; c < 4; ++c) acc[a][b][c] = 0.f;

    const int sx  = lane & 7;
    const int hiA = lane >> 4;
    const int rA  = wm * 32 + (lane & 15);
    const int hiB = (lane >> 3) & 1;
    const int rB  = wn * 64 + ((lane >> 4) & 1) * 8 + (lane & 7);
    const uint32_t aRow0 = (uint32_t)(rA << 7), aRow1 = (uint32_t)((rA + 16) << 7);
    uint32_t bRow[4];
#pragma unroll
    for (int i = 0; i < 4; ++i) bRow[i] = (uint32_t)((rB + i * 16) << 7);

    auto compute_stage = [&](int buf) {
        const uint32_t base = dataB + (uint32_t)buf * G_STAGE;
        const uint32_t Ab = base, Bb = base + 16384;
#pragma unroll
        for (int kk = 0; kk < 4; ++kk) {
            const uint32_t ao = (uint32_t)(((2 * kk + hiA) ^ sx) << 4);
            const uint32_t bo = (uint32_t)(((2 * kk + hiB) ^ sx) << 4);
            uint32_t a[2][4];
            ldsm4(a[0], Ab + aRow0 + ao);
            ldsm4(a[1], Ab + aRow1 + ao);
            uint32_t bf[4][4];
#pragma unroll
            for (int i16 = 0; i16 < 4; ++i16)
                ldsm4(bf[i16], Bb + bRow[i16] + bo);
#pragma unroll
            for (int im = 0; im < 2; ++im)
#pragma unroll
                for (int j = 0; j < 8; ++j)
                    mma16816(acc[im][j], a[im],
                             bf[j >> 1][(j & 1) * 2], bf[j >> 1][(j & 1) * 2 + 1]);
        }
    };

    const int NK = F_DIM / KSTAGE;   // 64
    load_stage(0, 0);
    load_stage(1, 1);
    int bc = 0, bl = 2;
    for (int kt = 0; kt < NK; ++kt) {
        if (kt < NK - 1) cp_wait<1>();
        else             cp_wait<0>();
        __syncthreads();
        if (kt + 2 < NK) {
            load_stage(bl, kt + 2);
            bl = (bl == 2) ? 0 : bl + 1;
        }
        compute_stage(bc);
        bc = (bc == 2) ? 0 : bc + 1;
    }

    const int mbase = mtile * 128 + wm * 32 + (lane >> 2);
    const int dbase = ntile * 128 + wn * 64 + (lane & 3) * 2;
#pragma unroll
    for (int im = 0; im < 2; ++im)
#pragma unroll
        for (int j = 0; j < 8; ++j)
#pragma unroll
            for (int hh = 0; hh < 2; ++hh) {
                int m = mbase + im * 16 + hh * 8;
                if (m < cnt) {
                    float2 v;
                    v.x = acc[im][j][hh * 2];
                    v.y = acc[im][j][hh * 2 + 1];
                    *reinterpret_cast<float2*>(
                        &g_ys[(size_t)(off + m) * D_DIM + dbase + j * 8]) = v;
                }
            }
}

// ---------------- combine (residual + weighted expert outputs) + counter reset ----
__global__ void __launch_bounds__(256) combine_kernel(const float* __restrict__ x,
                                                      float* __restrict__ out) {
    const int t = blockIdx.x;
    if (blockIdx.x == 0 && threadIdx.x < E_EXP) g_cnt[threadIdx.x] = 0;  // reset for next call
    const int s0 = g_slot[2 * t], s1 = g_slot[2 * t + 1];
    const float g0 = g_gw[2 * t], g1 = g_gw[2 * t + 1];
    const int d = threadIdx.x * 4;
    float4 xv = *reinterpret_cast<const float4*>(x + (size_t)t * D_DIM + d);
    float4 y0 = *reinterpret_cast<const float4*>(g_ys + (size_t)s0 * D_DIM + d);
    float4 y1 = *reinterpret_cast<const float4*>(g_ys + (size_t)s1 * D_DIM + d);
    float4 o;
    o.x = xv.x + g0 * y0.x + g1 * y1.x;
    o.y = xv.y + g0 * y0.y + g1 * y1.y;
    o.z = xv.z + g0 * y0.z + g1 * y1.z;
    o.w = xv.w + g0 * y0.w + g1 * y1.w;
    *reinterpret_cast<float4*>(out + (size_t)t * D_DIM + d) = o;
}

// ---------------- launch (two streams: conv overlaps gate/scan/gemm1) ----------------
extern "C" void kernel_launch(void* const* d_in, const int* in_sizes, int n_in,
                              void* d_out, int out_size) {
    (void)in_sizes; (void)n_in; (void)out_size;
    const float* x      = (const float*)d_in[0];
    const float* gate_w = (const float*)d_in[1];
    const float* ln_w   = (const float*)d_in[2];
    const float* w1     = (const float*)d_in[3];
    const float* w3     = (const float*)d_in[4];
    const float* w2     = (const float*)d_in[5];
    float* out = (float*)d_out;

    cudaFuncSetAttribute(gemm1_kernel, cudaFuncAttributeMaxDynamicSharedMemorySize, G_SMEM);
    cudaFuncSetAttribute(gemm2_kernel, cudaFuncAttributeMaxDynamicSharedMemorySize, G_SMEM);

    // Fresh side stream + events each call (created outside capture semantics concerns;
    // few calls total, intentionally not destroyed to keep captured graph nodes valid).
    cudaStream_t s1;
    cudaStreamCreateWithFlags(&s1, cudaStreamNonBlocking);
    cudaEvent_t evRoot, evA, evB, evC;
    cudaEventCreateWithFlags(&evRoot, cudaEventDisableTiming);
    cudaEventCreateWithFlags(&evA, cudaEventDisableTiming);
    cudaEventCreateWithFlags(&evB, cudaEventDisableTiming);
    cudaEventCreateWithFlags(&evC, cudaEventDisableTiming);

    // fork side stream from capture origin (legacy default stream)
    cudaEventRecord(evRoot, 0);
    cudaStreamWaitEvent(s1, evRoot, 0);

    // side stream: weight conversion
    const int C13_BLOCKS = 4 * (F_DIM * D_DIM) / 1024;     // 4 experts per launch
    conv13_kernel<<<C13_BLOCKS, 256, 0, s1>>>(w1, w3, ln_w, 0);
    cudaEventRecord(evA, s1);
    conv13_kernel<<<C13_BLOCKS, 256, 0, s1>>>(w1, w3, ln_w, 4);
    cudaEventRecord(evB, s1);
    conv2_kernel<<<(E_EXP * D_DIM * F_DIM) / 1024, 256, 0, s1>>>(w2);
    cudaEventRecord(evC, s1);

    // main stream: gating / routing, then GEMMs gated on conversion progress
    gate_kernel<<<T_TOK / 8, 256>>>(x, gate_w);
    scan_scatter_kernel<<<1, 1024>>>();
    cudaStreamWaitEvent(0, evA, 0);
    gemm1_kernel<<<dim3(F_DIM / 64, T_TOK / 128, 4), 256, G_SMEM>>>(0);
    cudaStreamWaitEvent(0, evB, 0);
    gemm1_kernel<<<dim3(F_DIM / 64, T_TOK / 128, 4), 256, G_SMEM>>>(4);
    cudaStreamWaitEvent(0, evC, 0);   // also rejoins s1 into the capture graph
    gemm2_kernel<<<dim3(D_DIM / 128, T_TOK / 128, E_EXP), 256, G_SMEM>>>();
    combine_kernel<<<T_TOK, 256>>>(x, out);
}